// round 3
// baseline (speedup 1.0000x reference)
#include <cuda_runtime.h>
#include <cstddef>

#define HH 1024
#define II 256
#define OO 256
#define BB 64
#define TT 512
#define MAXR 20     // padded rows per CTA in SMEM (actual nrows <= 18)
#define NPAIR 9     // row-pair accumulators per thread

// -------- static device scratch ----------
__device__ float g_xproj[(size_t)TT * HH * BB];   // [t][h][b]
__device__ float g_hall [(size_t)TT * HH * BB];   // slot t holds h_{t+1}, [h][b]
__device__ float g_outs [(size_t)TT * OO * BB];   // [t][o][b]
__device__ unsigned g_arrive[256];                // per-CTA arrival flags

// -------- packed f32x2 helpers ----------
__device__ __forceinline__ unsigned long long pack2(float w) {
    unsigned long long r; unsigned u = __float_as_uint(w);
    asm("mov.b64 %0, {%1, %1};" : "=l"(r) : "r"(u));
    return r;
}
__device__ __forceinline__ void fma2(unsigned long long& d, unsigned long long a, unsigned long long b) {
    asm("fma.rn.f32x2 %0, %1, %2, %3;" : "=l"(d) : "l"(a), "l"(b), "l"(d));
}
__device__ __forceinline__ unsigned long long add2(unsigned long long a, unsigned long long b) {
    unsigned long long r;
    asm("add.rn.f32x2 %0, %1, %2;" : "=l"(r) : "l"(a), "l"(b));
    return r;
}
__device__ __forceinline__ void unpack2(float& lo, float& hi, unsigned long long v) {
    unsigned a, b;
    asm("mov.b64 {%0, %1}, %2;" : "=r"(a), "=r"(b) : "l"(v));
    lo = __uint_as_float(a); hi = __uint_as_float(b);
}

// ==========================================================================
// Kernel 0: zero the barrier flags (every launch, before the scan)
// ==========================================================================
__global__ void barrier_init_kernel() {
    g_arrive[threadIdx.x] = 0u;
}

// ==========================================================================
// Kernel 1: x_proj[t][h][b] = sum_i inputs[b][t][i] * w_in[h][i] + b_in[h]
// ==========================================================================
__global__ void __launch_bounds__(256) xproj_kernel(
    const float* __restrict__ inp, const float* __restrict__ w_in,
    const float* __restrict__ b_in)
{
    __shared__ float As[32][68];   // [i][h]
    __shared__ float Bs[32][68];   // [i][b]
    const int t = blockIdx.y;
    const int hbase = blockIdx.x << 6;
    const int tid = threadIdx.x;
    const int hg = tid >> 5;       // 8 h rows each
    const int bg = tid & 31;       // b pair 2*bg

    unsigned long long acc[4][2];
#pragma unroll
    for (int p = 0; p < 4; ++p) { acc[p][0] = 0ull; acc[p][1] = 0ull; }

    for (int ic = 0; ic < II; ic += 32) {
#pragma unroll
        for (int n = tid; n < 64 * 32; n += 256) {
            int h = n >> 5, i = n & 31;
            As[i][h] = w_in[(size_t)(hbase + h) * II + ic + i];
        }
#pragma unroll
        for (int n = tid; n < 64 * 32; n += 256) {
            int b = n >> 5, i = n & 31;
            Bs[i][b] = inp[(size_t)b * (TT * II) + (size_t)t * II + ic + i];
        }
        __syncthreads();
#pragma unroll
        for (int i = 0; i < 32; ++i) {
            ulonglong2 w01 = *reinterpret_cast<const ulonglong2*>(&As[i][hg << 3]);
            ulonglong2 w23 = *reinterpret_cast<const ulonglong2*>(&As[i][(hg << 3) + 4]);
            float2 xv = *reinterpret_cast<const float2*>(&Bs[i][bg << 1]);
            unsigned long long x0 = pack2(xv.x), x1 = pack2(xv.y);
            fma2(acc[0][0], w01.x, x0); fma2(acc[0][1], w01.x, x1);
            fma2(acc[1][0], w01.y, x0); fma2(acc[1][1], w01.y, x1);
            fma2(acc[2][0], w23.x, x0); fma2(acc[2][1], w23.x, x1);
            fma2(acc[3][0], w23.y, x0); fma2(acc[3][1], w23.y, x1);
        }
        __syncthreads();
    }
#pragma unroll
    for (int p = 0; p < 4; ++p) {
        int h0 = hbase + (hg << 3) + 2 * p;
        float yA0, yA1, yB0, yB1;
        unpack2(yA0, yA1, acc[p][0]);
        unpack2(yB0, yB1, acc[p][1]);
        float bi0 = b_in[h0], bi1 = b_in[h0 + 1];
        size_t base = (size_t)t * (HH * BB) + (size_t)h0 * BB + (bg << 1);
        *reinterpret_cast<float2*>(g_xproj + base)      = make_float2(yA0 + bi0, yB0 + bi0);
        *reinterpret_cast<float2*>(g_xproj + base + BB) = make_float2(yA1 + bi1, yB1 + bi1);
    }
}

// ==========================================================================
// Kernel 2: persistent recurrent scan. grid = 2 b-halves x nrg row-groups.
// 512 threads: 16 k-slices x 32 lanes. f32x2 row-pair accumulators.
// Grid barrier = per-CTA flag stores + distributed polling (no atomics).
// ==========================================================================
__global__ void __launch_bounds__(512, 1) rnn_step_kernel(
    const float* __restrict__ w_rec, const float* __restrict__ b_rec,
    const float* __restrict__ w_out, const float* __restrict__ b_out,
    const float* __restrict__ scale, const float* __restrict__ shift)
{
    extern __shared__ float smem[];
    float* Ws = smem;                                            // [1024 * MAXR]
    unsigned long long* red =
        reinterpret_cast<unsigned long long*>(smem + HH * MAXR); // [16][NPAIR][32]

    const int tid = threadIdx.x;
    const int cta = blockIdx.x;
    const int ncta = gridDim.x;
    const int nrg = ncta >> 1;
    const int rg = cta >> 1;
    const int bhalf = cta & 1;
    const int base_r = 1280 / nrg;
    const int extra = 1280 - base_r * nrg;
    const int row0 = rg * base_r + (rg < extra ? rg : extra);
    const int nrows = base_r + (rg < extra ? 1 : 0);

    // zero then stage this CTA's weight rows once ([k][r], r stride MAXR)
    for (int idx = tid; idx < HH * MAXR; idx += 512) Ws[idx] = 0.f;
    __syncthreads();
    for (int r = 0; r < nrows; ++r) {
        int gr = row0 + r;
        const float* src = (gr < HH) ? (w_rec + (size_t)gr * HH)
                                     : (w_out + (size_t)(gr - HH) * HH);
        for (int k = tid; k < HH; k += 512)
            Ws[k * MAXR + r] = src[k];
    }
    __syncthreads();

    const int lane = tid & 31;
    const int ks = tid >> 5;              // 0..15, 64 k each
    const int k0 = ks << 6;
    const int bglob = (bhalf << 5) + lane;

    // ---- epilogue role
    const bool has_ep = (tid < NPAIR * 32);
    const int p_ep = tid >> 5;
    const int b_ep = tid & 31;
    const int bg_ep = (bhalf << 5) + b_ep;
    int gr0 = 0, gr1 = 0;
    bool v0 = false, v1 = false, rec0 = false, rec1 = false;
    float m0 = 0, a0 = 0, s0 = 0, m1 = 0, a1 = 0, s1 = 0;
    if (has_ep) {
        int r0l = 2 * p_ep, r1l = 2 * p_ep + 1;
        v0 = r0l < nrows; v1 = r1l < nrows;
        gr0 = row0 + r0l; gr1 = row0 + r1l;
        if (v0) {
            if (gr0 < HH) { rec0 = true; a0 = b_rec[gr0]; }
            else { m0 = scale[gr0 - HH]; a0 = b_out[gr0 - HH]; s0 = shift[gr0 - HH]; }
        }
        if (v1) {
            if (gr1 < HH) { rec1 = true; a1 = b_rec[gr1]; }
            else { m1 = scale[gr1 - HH]; a1 = b_out[gr1 - HH]; s1 = shift[gr1 - HH]; }
        }
    }

    volatile unsigned* arr = (volatile unsigned*)g_arrive;

    for (int j = 0; j <= TT; ++j) {
        // prefetch epilogue x (rec rows) — overlaps with FMA loop
        float x0 = 0.f, x1 = 0.f;
        if (has_ep && j < TT) {
            if (v0 && rec0) x0 = g_xproj[(size_t)j * (HH * BB) + (size_t)gr0 * BB + bg_ep];
            if (v1 && rec1) x1 = g_xproj[(size_t)j * (HH * BB) + (size_t)gr1 * BB + bg_ep];
        }

        unsigned long long acc[NPAIR];
#pragma unroll
        for (int p = 0; p < NPAIR; ++p) acc[p] = 0ull;

        if (j > 0) {
            const float* hp = g_hall + (size_t)(j - 1) * (HH * BB) + (size_t)k0 * BB + bglob;
            const float* wp = Ws + k0 * MAXR;
            float hbuf[16];
#pragma unroll
            for (int u = 0; u < 16; ++u) hbuf[u] = hp[u * BB];
#pragma unroll
            for (int kk = 0; kk < 64; kk += 16) {
                float hn[16];
                if (kk + 16 < 64) {
#pragma unroll
                    for (int u = 0; u < 16; ++u) hn[u] = hp[(kk + 16 + u) * BB];
                }
#pragma unroll
                for (int u = 0; u < 16; ++u) {
                    unsigned long long hv = pack2(hbuf[u]);
                    const float* w = wp + (kk + u) * MAXR;
                    ulonglong2 wA = *reinterpret_cast<const ulonglong2*>(w);
                    ulonglong2 wB = *reinterpret_cast<const ulonglong2*>(w + 4);
                    ulonglong2 wC = *reinterpret_cast<const ulonglong2*>(w + 8);
                    ulonglong2 wD = *reinterpret_cast<const ulonglong2*>(w + 12);
                    unsigned long long wE = *reinterpret_cast<const unsigned long long*>(w + 16);
                    fma2(acc[0], wA.x, hv); fma2(acc[1], wA.y, hv);
                    fma2(acc[2], wB.x, hv); fma2(acc[3], wB.y, hv);
                    fma2(acc[4], wC.x, hv); fma2(acc[5], wC.y, hv);
                    fma2(acc[6], wD.x, hv); fma2(acc[7], wD.y, hv);
                    fma2(acc[8], wE, hv);
                }
                if (kk + 16 < 64) {
#pragma unroll
                    for (int u = 0; u < 16; ++u) hbuf[u] = hn[u];
                }
            }
        }

        // k-slice reduction through SMEM
#pragma unroll
        for (int p = 0; p < NPAIR; ++p)
            red[(ks * NPAIR + p) * 32 + lane] = acc[p];
        __syncthreads();

        if (has_ep) {
            unsigned long long s = red[p_ep * 32 + b_ep];
#pragma unroll
            for (int q = 1; q < 16; ++q)
                s = add2(s, red[(q * NPAIR + p_ep) * 32 + b_ep]);
            float y0, y1; unpack2(y0, y1, s);
            if (v0) {
                if (rec0) {
                    if (j < TT)
                        g_hall[(size_t)j * (HH * BB) + (size_t)gr0 * BB + bg_ep] =
                            fmaxf(y0 + a0 + x0, 0.0f);
                } else if (j > 0) {
                    g_outs[(size_t)(j - 1) * (OO * BB) + (size_t)(gr0 - HH) * BB + bg_ep] =
                        m0 * (y0 + a0) - s0;
                }
            }
            if (v1) {
                if (rec1) {
                    if (j < TT)
                        g_hall[(size_t)j * (HH * BB) + (size_t)gr1 * BB + bg_ep] =
                            fmaxf(y1 + a1 + x1, 0.0f);
                } else if (j > 0) {
                    g_outs[(size_t)(j - 1) * (OO * BB) + (size_t)(gr1 - HH) * BB + bg_ep] =
                        m1 * (y1 + a1) - s1;
                }
            }
        }

        // ---- grid barrier: per-CTA flag + distributed poll (no atomics) ----
        __syncthreads();
        if (tid == 0) {
            __threadfence();
            arr[cta] = (unsigned)(j + 1);
        }
        if (tid < ncta) {
            while (arr[tid] < (unsigned)(j + 1)) { }
            __threadfence();
        }
        __syncthreads();
    }
}

// ==========================================================================
// Kernel 3: batched plane transpose  src[t][r][c] -> dst[c][t*R + r]
// ==========================================================================
__global__ void transpose_kernel(float* __restrict__ dst, int R, int which)
{
    __shared__ float tile[32][33];
    const float* src = which ? g_hall : g_outs;
    const int t = blockIdx.z;
    const int r0 = blockIdx.x << 5, c0 = blockIdx.y << 5;
    const int x = threadIdx.x, y = threadIdx.y;
    const float* s = src + (size_t)t * R * BB;
#pragma unroll
    for (int jj = 0; jj < 32; jj += 8)
        tile[y + jj][x] = s[(size_t)(r0 + y + jj) * BB + c0 + x];
    __syncthreads();
    const size_t TR = (size_t)TT * R;
#pragma unroll
    for (int jj = 0; jj < 32; jj += 8)
        dst[(size_t)(c0 + y + jj) * TR + (size_t)t * R + r0 + x] = tile[x][y + jj];
}

// ==========================================================================
extern "C" void kernel_launch(void* const* d_in, const int* in_sizes, int n_in,
                              void* d_out, int out_size)
{
    (void)in_sizes; (void)n_in; (void)out_size;
    const float* inputs = (const float*)d_in[0];
    const float* w_rec  = (const float*)d_in[1];
    const float* b_rec  = (const float*)d_in[2];
    const float* w_in   = (const float*)d_in[3];
    const float* b_in   = (const float*)d_in[4];
    const float* w_out  = (const float*)d_in[5];
    const float* b_out  = (const float*)d_in[6];
    const float* scale  = (const float*)d_in[7];
    const float* shift  = (const float*)d_in[8];
    float* out = (float*)d_out;

    barrier_init_kernel<<<1, 256>>>();
    xproj_kernel<<<dim3(HH / 64, TT), 256>>>(inputs, w_in, b_in);

    int dev = 0, sms = 148;
    cudaGetDevice(&dev);
    cudaDeviceGetAttribute(&sms, cudaDevAttrMultiProcessorCount, dev);
    int ncta = sms & ~1;
    if (ncta > 256) ncta = 256;

    const int smem_bytes = HH * MAXR * 4 + 16 * NPAIR * 32 * 8;   // 81920 + 36864
    cudaFuncSetAttribute(rnn_step_kernel,
                         cudaFuncAttributeMaxDynamicSharedMemorySize, smem_bytes);
    rnn_step_kernel<<<ncta, 512, smem_bytes>>>(w_rec, b_rec, w_out, b_out, scale, shift);

    transpose_kernel<<<dim3(OO / 32, BB / 32, TT), dim3(32, 8)>>>(out, OO, 0);
    transpose_kernel<<<dim3(HH / 32, BB / 32, TT), dim3(32, 8)>>>(
        out + (size_t)BB * TT * OO, HH, 1);
}

// round 4
// speedup vs baseline: 1.5162x; 1.5162x over previous
#include <cuda_runtime.h>
#include <cstddef>

#define HH 1024
#define II 256
#define OO 256
#define BB 64
#define TT 512
#define MAXR 20     // padded rows per CTA in SMEM (actual nrows <= 18)
#define NPAIR 9     // row-pair accumulators per thread

// -------- static device scratch ----------
__device__ float g_xproj[(size_t)TT * HH * BB];   // [t][h][b]
__device__ float g_hall [(size_t)TT * HH * BB];   // slot t holds h_{t+1}, [h][b]
__device__ float g_outs [(size_t)TT * OO * BB];   // [t][o][b]
__device__ unsigned g_grp[256];                   // 8 group counters, 128B apart (idx g*32)
__device__ unsigned g_root;                       // root counter (monotonic)
__device__ volatile unsigned g_gen;               // release generation

// -------- packed f32x2 helpers ----------
__device__ __forceinline__ unsigned long long pack2(float w) {
    unsigned long long r; unsigned u = __float_as_uint(w);
    asm("mov.b64 %0, {%1, %1};" : "=l"(r) : "r"(u));
    return r;
}
__device__ __forceinline__ void fma2(unsigned long long& d, unsigned long long a, unsigned long long b) {
    asm("fma.rn.f32x2 %0, %1, %2, %3;" : "=l"(d) : "l"(a), "l"(b), "l"(d));
}
__device__ __forceinline__ unsigned long long add2(unsigned long long a, unsigned long long b) {
    unsigned long long r;
    asm("add.rn.f32x2 %0, %1, %2;" : "=l"(r) : "l"(a), "l"(b));
    return r;
}
__device__ __forceinline__ void unpack2(float& lo, float& hi, unsigned long long v) {
    unsigned a, b;
    asm("mov.b64 {%0, %1}, %2;" : "=r"(a), "=r"(b) : "l"(v));
    lo = __uint_as_float(a); hi = __uint_as_float(b);
}

// ==========================================================================
// Kernel 0: zero barrier state (every launch, before the scan)
// ==========================================================================
__global__ void barrier_init_kernel() {
    g_grp[threadIdx.x] = 0u;
    if (threadIdx.x == 0) { g_root = 0u; g_gen = 0u; }
}

// ==========================================================================
// Kernel 1: x_proj[t][h][b] = sum_i inputs[b][t][i] * w_in[h][i] + b_in[h]
// ==========================================================================
__global__ void __launch_bounds__(256) xproj_kernel(
    const float* __restrict__ inp, const float* __restrict__ w_in,
    const float* __restrict__ b_in)
{
    __shared__ float As[32][68];   // [i][h]
    __shared__ float Bs[32][68];   // [i][b]
    const int t = blockIdx.y;
    const int hbase = blockIdx.x << 6;
    const int tid = threadIdx.x;
    const int hg = tid >> 5;       // 8 h rows each
    const int bg = tid & 31;       // b pair 2*bg

    unsigned long long acc[4][2];
#pragma unroll
    for (int p = 0; p < 4; ++p) { acc[p][0] = 0ull; acc[p][1] = 0ull; }

    for (int ic = 0; ic < II; ic += 32) {
#pragma unroll
        for (int n = tid; n < 64 * 32; n += 256) {
            int h = n >> 5, i = n & 31;
            As[i][h] = w_in[(size_t)(hbase + h) * II + ic + i];
        }
#pragma unroll
        for (int n = tid; n < 64 * 32; n += 256) {
            int b = n >> 5, i = n & 31;
            Bs[i][b] = inp[(size_t)b * (TT * II) + (size_t)t * II + ic + i];
        }
        __syncthreads();
#pragma unroll
        for (int i = 0; i < 32; ++i) {
            ulonglong2 w01 = *reinterpret_cast<const ulonglong2*>(&As[i][hg << 3]);
            ulonglong2 w23 = *reinterpret_cast<const ulonglong2*>(&As[i][(hg << 3) + 4]);
            float2 xv = *reinterpret_cast<const float2*>(&Bs[i][bg << 1]);
            unsigned long long x0 = pack2(xv.x), x1 = pack2(xv.y);
            fma2(acc[0][0], w01.x, x0); fma2(acc[0][1], w01.x, x1);
            fma2(acc[1][0], w01.y, x0); fma2(acc[1][1], w01.y, x1);
            fma2(acc[2][0], w23.x, x0); fma2(acc[2][1], w23.x, x1);
            fma2(acc[3][0], w23.y, x0); fma2(acc[3][1], w23.y, x1);
        }
        __syncthreads();
    }
#pragma unroll
    for (int p = 0; p < 4; ++p) {
        int h0 = hbase + (hg << 3) + 2 * p;
        float yA0, yA1, yB0, yB1;
        unpack2(yA0, yA1, acc[p][0]);
        unpack2(yB0, yB1, acc[p][1]);
        float bi0 = b_in[h0], bi1 = b_in[h0 + 1];
        size_t base = (size_t)t * (HH * BB) + (size_t)h0 * BB + (bg << 1);
        *reinterpret_cast<float2*>(g_xproj + base)      = make_float2(yA0 + bi0, yB0 + bi0);
        *reinterpret_cast<float2*>(g_xproj + base + BB) = make_float2(yA1 + bi1, yB1 + bi1);
    }
}

// ==========================================================================
// Kernel 2: persistent recurrent scan. grid = 2 b-halves x nrg row-groups.
// 512 threads: 16 k-slices x 32 lanes. f32x2 row-pair accumulators.
// Grid barrier: 2-level hierarchical atomics + single release flag.
// ==========================================================================
__global__ void __launch_bounds__(512, 1) rnn_step_kernel(
    const float* __restrict__ w_rec, const float* __restrict__ b_rec,
    const float* __restrict__ w_out, const float* __restrict__ b_out,
    const float* __restrict__ scale, const float* __restrict__ shift)
{
    extern __shared__ float smem[];
    float* Ws = smem;                                            // [1024 * MAXR]
    unsigned long long* red =
        reinterpret_cast<unsigned long long*>(smem + HH * MAXR); // [16][NPAIR][32]

    const int tid = threadIdx.x;
    const int cta = blockIdx.x;
    const int ncta = gridDim.x;
    const int nrg = ncta >> 1;
    const int rg = cta >> 1;
    const int bhalf = cta & 1;
    const int base_r = 1280 / nrg;
    const int extra = 1280 - base_r * nrg;
    const int row0 = rg * base_r + (rg < extra ? rg : extra);
    const int nrows = base_r + (rg < extra ? 1 : 0);

    // barrier group constants
    const int grp = cta & 7;
    const unsigned gsize = (unsigned)(ncta >> 3) + ((grp < (ncta & 7)) ? 1u : 0u);

    // zero then stage this CTA's weight rows once ([k][r], r stride MAXR)
    for (int idx = tid; idx < HH * MAXR; idx += 512) Ws[idx] = 0.f;
    __syncthreads();
    for (int r = 0; r < nrows; ++r) {
        int gr = row0 + r;
        const float* src = (gr < HH) ? (w_rec + (size_t)gr * HH)
                                     : (w_out + (size_t)(gr - HH) * HH);
        for (int k = tid; k < HH; k += 512)
            Ws[k * MAXR + r] = src[k];
    }
    __syncthreads();

    const int lane = tid & 31;
    const int ks = tid >> 5;              // 0..15, 64 k each
    const int k0 = ks << 6;
    const int bglob = (bhalf << 5) + lane;

    // ---- epilogue role
    const bool has_ep = (tid < NPAIR * 32);
    const int p_ep = tid >> 5;
    const int b_ep = tid & 31;
    const int bg_ep = (bhalf << 5) + b_ep;
    int gr0 = 0, gr1 = 0;
    bool v0 = false, v1 = false, rec0 = false, rec1 = false;
    float m0 = 0, a0 = 0, s0 = 0, m1 = 0, a1 = 0, s1 = 0;
    if (has_ep) {
        int r0l = 2 * p_ep, r1l = 2 * p_ep + 1;
        v0 = r0l < nrows; v1 = r1l < nrows;
        gr0 = row0 + r0l; gr1 = row0 + r1l;
        if (v0) {
            if (gr0 < HH) { rec0 = true; a0 = b_rec[gr0]; }
            else { m0 = scale[gr0 - HH]; a0 = b_out[gr0 - HH]; s0 = shift[gr0 - HH]; }
        }
        if (v1) {
            if (gr1 < HH) { rec1 = true; a1 = b_rec[gr1]; }
            else { m1 = scale[gr1 - HH]; a1 = b_out[gr1 - HH]; s1 = shift[gr1 - HH]; }
        }
    }

    for (int j = 0; j <= TT; ++j) {
        // prefetch epilogue x (rec rows) — overlaps with FMA loop
        float x0 = 0.f, x1 = 0.f;
        if (has_ep && j < TT) {
            if (v0 && rec0) x0 = g_xproj[(size_t)j * (HH * BB) + (size_t)gr0 * BB + bg_ep];
            if (v1 && rec1) x1 = g_xproj[(size_t)j * (HH * BB) + (size_t)gr1 * BB + bg_ep];
        }

        unsigned long long acc[NPAIR];
#pragma unroll
        for (int p = 0; p < NPAIR; ++p) acc[p] = 0ull;

        if (j > 0) {
            const float* hp = g_hall + (size_t)(j - 1) * (HH * BB) + (size_t)k0 * BB + bglob;
            const float* wp = Ws + k0 * MAXR;
            float hbuf[8];
#pragma unroll
            for (int u = 0; u < 8; ++u) hbuf[u] = hp[u * BB];
#pragma unroll
            for (int kk = 0; kk < 64; kk += 8) {
                float hn[8];
                if (kk + 8 < 64) {
#pragma unroll
                    for (int u = 0; u < 8; ++u) hn[u] = hp[(kk + 8 + u) * BB];
                }
#pragma unroll
                for (int u = 0; u < 8; ++u) {
                    unsigned long long hv = pack2(hbuf[u]);
                    const float* w = wp + (kk + u) * MAXR;
                    ulonglong2 wA = *reinterpret_cast<const ulonglong2*>(w);
                    ulonglong2 wB = *reinterpret_cast<const ulonglong2*>(w + 4);
                    ulonglong2 wC = *reinterpret_cast<const ulonglong2*>(w + 8);
                    ulonglong2 wD = *reinterpret_cast<const ulonglong2*>(w + 12);
                    unsigned long long wE = *reinterpret_cast<const unsigned long long*>(w + 16);
                    fma2(acc[0], wA.x, hv); fma2(acc[1], wA.y, hv);
                    fma2(acc[2], wB.x, hv); fma2(acc[3], wB.y, hv);
                    fma2(acc[4], wC.x, hv); fma2(acc[5], wC.y, hv);
                    fma2(acc[6], wD.x, hv); fma2(acc[7], wD.y, hv);
                    fma2(acc[8], wE, hv);
                }
                if (kk + 8 < 64) {
#pragma unroll
                    for (int u = 0; u < 8; ++u) hbuf[u] = hn[u];
                }
            }
        }

        // k-slice reduction through SMEM
#pragma unroll
        for (int p = 0; p < NPAIR; ++p)
            red[(ks * NPAIR + p) * 32 + lane] = acc[p];
        __syncthreads();

        if (has_ep) {
            unsigned long long s = red[p_ep * 32 + b_ep];
#pragma unroll
            for (int q = 1; q < 16; ++q)
                s = add2(s, red[(q * NPAIR + p_ep) * 32 + b_ep]);
            float y0, y1; unpack2(y0, y1, s);
            if (v0) {
                if (rec0) {
                    if (j < TT)
                        g_hall[(size_t)j * (HH * BB) + (size_t)gr0 * BB + bg_ep] =
                            fmaxf(y0 + a0 + x0, 0.0f);
                } else if (j > 0) {
                    g_outs[(size_t)(j - 1) * (OO * BB) + (size_t)(gr0 - HH) * BB + bg_ep] =
                        m0 * (y0 + a0) - s0;
                }
            }
            if (v1) {
                if (rec1) {
                    if (j < TT)
                        g_hall[(size_t)j * (HH * BB) + (size_t)gr1 * BB + bg_ep] =
                            fmaxf(y1 + a1 + x1, 0.0f);
                } else if (j > 0) {
                    g_outs[(size_t)(j - 1) * (OO * BB) + (size_t)(gr1 - HH) * BB + bg_ep] =
                        m1 * (y1 + a1) - s1;
                }
            }
        }

        // ---- hierarchical grid barrier (monotonic counters) ----
        __syncthreads();
        if (tid == 0) {
            __threadfence();
            unsigned old = atomicAdd(&g_grp[grp << 5], 1u);
            if (old + 1u == (unsigned)(j + 1) * gsize) {
                unsigned r = atomicAdd(&g_root, 1u);
                if (r + 1u == (unsigned)(j + 1) * 8u) {
                    __threadfence();
                    g_gen = (unsigned)(j + 1);
                }
            }
            while (g_gen < (unsigned)(j + 1)) { }
            __threadfence();
        }
        __syncthreads();
    }
}

// ==========================================================================
// Kernel 3: batched plane transpose  src[t][r][c] -> dst[c][t*R + r]
// ==========================================================================
__global__ void transpose_kernel(float* __restrict__ dst, int R, int which)
{
    __shared__ float tile[32][33];
    const float* src = which ? g_hall : g_outs;
    const int t = blockIdx.z;
    const int r0 = blockIdx.x << 5, c0 = blockIdx.y << 5;
    const int x = threadIdx.x, y = threadIdx.y;
    const float* s = src + (size_t)t * R * BB;
#pragma unroll
    for (int jj = 0; jj < 32; jj += 8)
        tile[y + jj][x] = s[(size_t)(r0 + y + jj) * BB + c0 + x];
    __syncthreads();
    const size_t TR = (size_t)TT * R;
#pragma unroll
    for (int jj = 0; jj < 32; jj += 8)
        dst[(size_t)(c0 + y + jj) * TR + (size_t)t * R + r0 + x] = tile[x][y + jj];
}

// ==========================================================================
extern "C" void kernel_launch(void* const* d_in, const int* in_sizes, int n_in,
                              void* d_out, int out_size)
{
    (void)in_sizes; (void)n_in; (void)out_size;
    const float* inputs = (const float*)d_in[0];
    const float* w_rec  = (const float*)d_in[1];
    const float* b_rec  = (const float*)d_in[2];
    const float* w_in   = (const float*)d_in[3];
    const float* b_in   = (const float*)d_in[4];
    const float* w_out  = (const float*)d_in[5];
    const float* b_out  = (const float*)d_in[6];
    const float* scale  = (const float*)d_in[7];
    const float* shift  = (const float*)d_in[8];
    float* out = (float*)d_out;

    barrier_init_kernel<<<1, 256>>>();
    xproj_kernel<<<dim3(HH / 64, TT), 256>>>(inputs, w_in, b_in);

    int dev = 0, sms = 148;
    cudaGetDevice(&dev);
    cudaDeviceGetAttribute(&sms, cudaDevAttrMultiProcessorCount, dev);
    int ncta = sms & ~1;
    if (ncta > 152) ncta = 152;

    const int smem_bytes = HH * MAXR * 4 + 16 * NPAIR * 32 * 8;   // 81920 + 36864
    cudaFuncSetAttribute(rnn_step_kernel,
                         cudaFuncAttributeMaxDynamicSharedMemorySize, smem_bytes);
    rnn_step_kernel<<<ncta, 512, smem_bytes>>>(w_rec, b_rec, w_out, b_out, scale, shift);

    transpose_kernel<<<dim3(OO / 32, BB / 32, TT), dim3(32, 8)>>>(out, OO, 0);
    transpose_kernel<<<dim3(HH / 32, BB / 32, TT), dim3(32, 8)>>>(
        out + (size_t)BB * TT * OO, HH, 1);
}

// round 5
// speedup vs baseline: 1.5216x; 1.0036x over previous
#include <cuda_runtime.h>
#include <cstddef>

#define HH 1024
#define II 256
#define OO 256
#define BB 64
#define TT 512
#define MAXR 16     // padded rows per CTA in SMEM (actual nrows <= 14)
#define NPAIR 7     // row-pair accumulators per thread

// -------- static device scratch ----------
__device__ float g_xproj[(size_t)TT * HH * BB];   // [t][h][b]
__device__ float g_hall [(size_t)TT * HH * BB];   // slot t holds h_{t+1}, [h][b]
__device__ float g_outs [(size_t)TT * OO * BB];   // [t][o][b]
__device__ unsigned g_grp[256];                   // 8 group counters, 128B apart
__device__ unsigned g_root;
__device__ volatile unsigned g_gen;

// -------- packed f32x2 helpers ----------
__device__ __forceinline__ unsigned long long pack2(float w) {
    unsigned long long r; unsigned u = __float_as_uint(w);
    asm("mov.b64 %0, {%1, %1};" : "=l"(r) : "r"(u));
    return r;
}
__device__ __forceinline__ void fma2(unsigned long long& d, unsigned long long a, unsigned long long b) {
    asm("fma.rn.f32x2 %0, %1, %2, %3;" : "=l"(d) : "l"(a), "l"(b), "l"(d));
}
__device__ __forceinline__ unsigned long long add2(unsigned long long a, unsigned long long b) {
    unsigned long long r;
    asm("add.rn.f32x2 %0, %1, %2;" : "=l"(r) : "l"(a), "l"(b));
    return r;
}
__device__ __forceinline__ void unpack2(float& lo, float& hi, unsigned long long v) {
    unsigned a, b;
    asm("mov.b64 {%0, %1}, %2;" : "=r"(a), "=r"(b) : "l"(v));
    lo = __uint_as_float(a); hi = __uint_as_float(b);
}

// ==========================================================================
// Kernel 0: zero barrier state
// ==========================================================================
__global__ void barrier_init_kernel() {
    g_grp[threadIdx.x] = 0u;
    if (threadIdx.x == 0) { g_root = 0u; g_gen = 0u; }
}

// ==========================================================================
// Kernel 1: x_proj[t][h][b] = sum_i inputs[b][t][i] * w_in[h][i] + b_in[h]
// ==========================================================================
__global__ void __launch_bounds__(256) xproj_kernel(
    const float* __restrict__ inp, const float* __restrict__ w_in,
    const float* __restrict__ b_in)
{
    __shared__ float As[32][68];   // [i][h]
    __shared__ float Bs[32][68];   // [i][b]
    const int t = blockIdx.y;
    const int hbase = blockIdx.x << 6;
    const int tid = threadIdx.x;
    const int hg = tid >> 5;       // 8 h rows each
    const int bg = tid & 31;       // b pair 2*bg

    unsigned long long acc[4][2];
#pragma unroll
    for (int p = 0; p < 4; ++p) { acc[p][0] = 0ull; acc[p][1] = 0ull; }

    for (int ic = 0; ic < II; ic += 32) {
#pragma unroll
        for (int n = tid; n < 64 * 32; n += 256) {
            int h = n >> 5, i = n & 31;
            As[i][h] = w_in[(size_t)(hbase + h) * II + ic + i];
        }
#pragma unroll
        for (int n = tid; n < 64 * 32; n += 256) {
            int b = n >> 5, i = n & 31;
            Bs[i][b] = inp[(size_t)b * (TT * II) + (size_t)t * II + ic + i];
        }
        __syncthreads();
#pragma unroll
        for (int i = 0; i < 32; ++i) {
            ulonglong2 w01 = *reinterpret_cast<const ulonglong2*>(&As[i][hg << 3]);
            ulonglong2 w23 = *reinterpret_cast<const ulonglong2*>(&As[i][(hg << 3) + 4]);
            float2 xv = *reinterpret_cast<const float2*>(&Bs[i][bg << 1]);
            unsigned long long x0 = pack2(xv.x), x1 = pack2(xv.y);
            fma2(acc[0][0], w01.x, x0); fma2(acc[0][1], w01.x, x1);
            fma2(acc[1][0], w01.y, x0); fma2(acc[1][1], w01.y, x1);
            fma2(acc[2][0], w23.x, x0); fma2(acc[2][1], w23.x, x1);
            fma2(acc[3][0], w23.y, x0); fma2(acc[3][1], w23.y, x1);
        }
        __syncthreads();
    }
#pragma unroll
    for (int p = 0; p < 4; ++p) {
        int h0 = hbase + (hg << 3) + 2 * p;
        float yA0, yA1, yB0, yB1;
        unpack2(yA0, yA1, acc[p][0]);
        unpack2(yB0, yB1, acc[p][1]);
        float bi0 = b_in[h0], bi1 = b_in[h0 + 1];
        size_t base = (size_t)t * (HH * BB) + (size_t)h0 * BB + (bg << 1);
        *reinterpret_cast<float2*>(g_xproj + base)      = make_float2(yA0 + bi0, yB0 + bi0);
        *reinterpret_cast<float2*>(g_xproj + base + BB) = make_float2(yA1 + bi1, yB1 + bi1);
    }
}

// ==========================================================================
// Kernel 2: persistent recurrent scan (W_rec ONLY — 1024 rows).
// grid = 2 b-halves x nrg row-groups; 512 threads = 16 k-slices x 32 lanes.
// ==========================================================================
__global__ void __launch_bounds__(512, 1) rnn_step_kernel(
    const float* __restrict__ w_rec, const float* __restrict__ b_rec)
{
    extern __shared__ float smem[];
    float* Ws = smem;                                            // [1024 * MAXR]
    unsigned long long* red =
        reinterpret_cast<unsigned long long*>(smem + HH * MAXR); // [16][NPAIR][32]

    const int tid = threadIdx.x;
    const int cta = blockIdx.x;
    const int ncta = gridDim.x;
    const int nrg = ncta >> 1;
    const int rg = cta >> 1;
    const int bhalf = cta & 1;
    const int base_r = HH / nrg;
    const int extra = HH - base_r * nrg;
    const int row0 = rg * base_r + (rg < extra ? rg : extra);
    const int nrows = base_r + (rg < extra ? 1 : 0);

    const int grp = cta & 7;
    const unsigned gsize = (unsigned)(ncta >> 3) + ((grp < (ncta & 7)) ? 1u : 0u);

    // zero then stage weight rows once ([k][r], r stride MAXR)
    for (int idx = tid; idx < HH * MAXR; idx += 512) Ws[idx] = 0.f;
    __syncthreads();
    for (int r = 0; r < nrows; ++r) {
        const float* src = w_rec + (size_t)(row0 + r) * HH;
        for (int k = tid; k < HH; k += 512)
            Ws[k * MAXR + r] = src[k];
    }
    __syncthreads();

    const int lane = tid & 31;
    const int ks = tid >> 5;              // 0..15, 64 k each
    const int k0 = ks << 6;
    const int bglob = (bhalf << 5) + lane;

    // ---- epilogue role: tid < 224 handles (row-pair p_ep, batch b_ep)
    const bool has_ep = (tid < NPAIR * 32);
    const int p_ep = tid >> 5;
    const int b_ep = tid & 31;
    const int bg_ep = (bhalf << 5) + b_ep;
    int gr0 = 0, gr1 = 0;
    bool v0 = false, v1 = false;
    float a0 = 0.f, a1 = 0.f;
    if (has_ep) {
        int r0l = 2 * p_ep, r1l = 2 * p_ep + 1;
        v0 = r0l < nrows; v1 = r1l < nrows;
        gr0 = row0 + r0l; gr1 = row0 + r1l;
        if (v0) a0 = b_rec[gr0];
        if (v1) a1 = b_rec[gr1];
    }

#define LOADH(dst, off) do { \
    _Pragma("unroll") for (int u = 0; u < 16; ++u) (dst)[u] = hp[((off) + u) * BB]; } while (0)

#define COMPUTE16(buf) do { \
    _Pragma("unroll") for (int u = 0; u < 16; ++u) { \
        unsigned long long hv = pack2((buf)[u]); \
        ulonglong2 wA = *reinterpret_cast<const ulonglong2*>(wp); \
        ulonglong2 wB = *reinterpret_cast<const ulonglong2*>(wp + 4); \
        ulonglong2 wC = *reinterpret_cast<const ulonglong2*>(wp + 8); \
        unsigned long long wD = *reinterpret_cast<const unsigned long long*>(wp + 12); \
        wp += MAXR; \
        fma2(acc[0], wA.x, hv); fma2(acc[1], wA.y, hv); \
        fma2(acc[2], wB.x, hv); fma2(acc[3], wB.y, hv); \
        fma2(acc[4], wC.x, hv); fma2(acc[5], wC.y, hv); \
        fma2(acc[6], wD, hv); } } while (0)

    for (int j = 0; j < TT; ++j) {
        // prefetch epilogue x — consumed after the FMA loop
        float x0 = 0.f, x1 = 0.f;
        if (has_ep) {
            if (v0) x0 = g_xproj[(size_t)j * (HH * BB) + (size_t)gr0 * BB + bg_ep];
            if (v1) x1 = g_xproj[(size_t)j * (HH * BB) + (size_t)gr1 * BB + bg_ep];
        }

        unsigned long long acc[NPAIR];
#pragma unroll
        for (int p = 0; p < NPAIR; ++p) acc[p] = 0ull;

        if (j > 0) {
            const float* hp = g_hall + (size_t)(j - 1) * (HH * BB) + (size_t)k0 * BB + bglob;
            const float* wp = Ws + k0 * MAXR;
            float hb0[16], hb1[16];
            LOADH(hb0, 0);
            LOADH(hb1, 16);
            COMPUTE16(hb0);
            LOADH(hb0, 32);
            COMPUTE16(hb1);
            LOADH(hb1, 48);
            COMPUTE16(hb0);
            COMPUTE16(hb1);
        }

        // k-slice reduction through SMEM
#pragma unroll
        for (int p = 0; p < NPAIR; ++p)
            red[(ks * NPAIR + p) * 32 + lane] = acc[p];
        __syncthreads();

        if (has_ep) {
            unsigned long long v[16];
#pragma unroll
            for (int q = 0; q < 16; ++q)
                v[q] = red[(q * NPAIR + p_ep) * 32 + b_ep];
            unsigned long long s01 = add2(add2(v[0], v[1]),  add2(v[2], v[3]));
            unsigned long long s23 = add2(add2(v[4], v[5]),  add2(v[6], v[7]));
            unsigned long long s45 = add2(add2(v[8], v[9]),  add2(v[10], v[11]));
            unsigned long long s67 = add2(add2(v[12], v[13]), add2(v[14], v[15]));
            unsigned long long s = add2(add2(s01, s23), add2(s45, s67));
            float y0, y1; unpack2(y0, y1, s);
            size_t base = (size_t)j * (HH * BB);
            if (v0) g_hall[base + (size_t)gr0 * BB + bg_ep] = fmaxf(y0 + a0 + x0, 0.0f);
            if (v1) g_hall[base + (size_t)gr1 * BB + bg_ep] = fmaxf(y1 + a1 + x1, 0.0f);
        }

        // ---- hierarchical grid barrier (skip after final step) ----
        __syncthreads();
        if (j < TT - 1) {
            if (tid == 0) {
                __threadfence();
                unsigned old = atomicAdd(&g_grp[grp << 5], 1u);
                if (old + 1u == (unsigned)(j + 1) * gsize) {
                    unsigned r = atomicAdd(&g_root, 1u);
                    if (r + 1u == (unsigned)(j + 1) * 8u) {
                        __threadfence();
                        g_gen = (unsigned)(j + 1);
                    }
                }
                while (g_gen < (unsigned)(j + 1)) { }
                __threadfence();
            }
            __syncthreads();
        }
    }
#undef LOADH
#undef COMPUTE16
}

// ==========================================================================
// Kernel 2b: out GEMM (off critical path).
// g_outs[t][o][b] = scale[o]*(sum_h w_out[o][h]*g_hall[t][h][b] + b_out[o]) - shift[o]
// grid (OO/64, TT), 256 threads, same micro-structure as xproj.
// ==========================================================================
__global__ void __launch_bounds__(256) outproj_kernel(
    const float* __restrict__ w_out, const float* __restrict__ b_out,
    const float* __restrict__ scale, const float* __restrict__ shift)
{
    __shared__ float As[32][68];   // [i][o]
    __shared__ float Bs[32][68];   // [i][b]
    const int t = blockIdx.y;
    const int obase = blockIdx.x << 6;
    const int tid = threadIdx.x;
    const int og = tid >> 5;       // 8 o rows each
    const int bg = tid & 31;       // b pair

    unsigned long long acc[4][2];
#pragma unroll
    for (int p = 0; p < 4; ++p) { acc[p][0] = 0ull; acc[p][1] = 0ull; }

    for (int kc = 0; kc < HH; kc += 32) {
#pragma unroll
        for (int n = tid; n < 64 * 32; n += 256) {
            int o = n >> 5, i = n & 31;
            As[i][o] = w_out[(size_t)(obase + o) * HH + kc + i];
        }
#pragma unroll
        for (int n = tid; n < 64 * 32; n += 256) {
            int b = n & 63, i = n >> 6;   // 32 rows of 64: i in 0..31 (n>>6 max 31)
            Bs[i][b] = g_hall[(size_t)t * (HH * BB) + (size_t)(kc + i) * BB + b];
        }
        __syncthreads();
#pragma unroll
        for (int i = 0; i < 32; ++i) {
            ulonglong2 w01 = *reinterpret_cast<const ulonglong2*>(&As[i][og << 3]);
            ulonglong2 w23 = *reinterpret_cast<const ulonglong2*>(&As[i][(og << 3) + 4]);
            float2 xv = *reinterpret_cast<const float2*>(&Bs[i][bg << 1]);
            unsigned long long x0 = pack2(xv.x), x1 = pack2(xv.y);
            fma2(acc[0][0], w01.x, x0); fma2(acc[0][1], w01.x, x1);
            fma2(acc[1][0], w01.y, x0); fma2(acc[1][1], w01.y, x1);
            fma2(acc[2][0], w23.x, x0); fma2(acc[2][1], w23.x, x1);
            fma2(acc[3][0], w23.y, x0); fma2(acc[3][1], w23.y, x1);
        }
        __syncthreads();
    }
#pragma unroll
    for (int p = 0; p < 4; ++p) {
        int o0 = obase + (og << 3) + 2 * p;
        float yA0, yA1, yB0, yB1;
        unpack2(yA0, yA1, acc[p][0]);   // o0, o0+1 @ b0
        unpack2(yB0, yB1, acc[p][1]);   // o0, o0+1 @ b1
        float m0 = scale[o0], m1 = scale[o0 + 1];
        float c0 = b_out[o0], c1 = b_out[o0 + 1];
        float s0 = shift[o0], s1 = shift[o0 + 1];
        size_t base = (size_t)t * (OO * BB) + (size_t)o0 * BB + (bg << 1);
        *reinterpret_cast<float2*>(g_outs + base) =
            make_float2(m0 * (yA0 + c0) - s0, m0 * (yB0 + c0) - s0);
        *reinterpret_cast<float2*>(g_outs + base + BB) =
            make_float2(m1 * (yA1 + c1) - s1, m1 * (yB1 + c1) - s1);
    }
}

// ==========================================================================
// Kernel 3: batched plane transpose  src[t][r][c] -> dst[c][t*R + r]
// ==========================================================================
__global__ void transpose_kernel(float* __restrict__ dst, int R, int which)
{
    __shared__ float tile[32][33];
    const float* src = which ? g_hall : g_outs;
    const int t = blockIdx.z;
    const int r0 = blockIdx.x << 5, c0 = blockIdx.y << 5;
    const int x = threadIdx.x, y = threadIdx.y;
    const float* s = src + (size_t)t * R * BB;
#pragma unroll
    for (int jj = 0; jj < 32; jj += 8)
        tile[y + jj][x] = s[(size_t)(r0 + y + jj) * BB + c0 + x];
    __syncthreads();
    const size_t TR = (size_t)TT * R;
#pragma unroll
    for (int jj = 0; jj < 32; jj += 8)
        dst[(size_t)(c0 + y + jj) * TR + (size_t)t * R + r0 + x] = tile[x][y + jj];
}

// ==========================================================================
extern "C" void kernel_launch(void* const* d_in, const int* in_sizes, int n_in,
                              void* d_out, int out_size)
{
    (void)in_sizes; (void)n_in; (void)out_size;
    const float* inputs = (const float*)d_in[0];
    const float* w_rec  = (const float*)d_in[1];
    const float* b_rec  = (const float*)d_in[2];
    const float* w_in   = (const float*)d_in[3];
    const float* b_in   = (const float*)d_in[4];
    const float* w_out  = (const float*)d_in[5];
    const float* b_out  = (const float*)d_in[6];
    const float* scale  = (const float*)d_in[7];
    const float* shift  = (const float*)d_in[8];
    float* out = (float*)d_out;

    barrier_init_kernel<<<1, 256>>>();
    xproj_kernel<<<dim3(HH / 64, TT), 256>>>(inputs, w_in, b_in);

    int dev = 0, sms = 148;
    cudaGetDevice(&dev);
    cudaDeviceGetAttribute(&sms, cudaDevAttrMultiProcessorCount, dev);
    int ncta = sms & ~1;
    if (ncta > 152) ncta = 152;

    const int smem_bytes = HH * MAXR * 4 + 16 * NPAIR * 32 * 8;   // 65536 + 28672
    cudaFuncSetAttribute(rnn_step_kernel,
                         cudaFuncAttributeMaxDynamicSharedMemorySize, smem_bytes);
    rnn_step_kernel<<<ncta, 512, smem_bytes>>>(w_rec, b_rec);

    outproj_kernel<<<dim3(OO / 64, TT), 256>>>(w_out, b_out, scale, shift);

    transpose_kernel<<<dim3(OO / 32, BB / 32, TT), dim3(32, 8)>>>(out, OO, 0);
    transpose_kernel<<<dim3(HH / 32, BB / 32, TT), dim3(32, 8)>>>(
        out + (size_t)BB * TT * OO, HH, 1);
}

// round 7
// speedup vs baseline: 1.6472x; 1.0825x over previous
#include <cuda_runtime.h>
#include <cstdint>
#include <cstddef>

#define HH 1024
#define II 256
#define OO 256
#define BB 64
#define TT 512
#define MAXR 16     // padded rows per CTA in SMEM (actual nrows <= 14)
#define NPAIR 7     // row-pair accumulators per thread

// -------- static device scratch ----------
__device__ float g_xproj[(size_t)TT * HH * BB];   // [t][h][b]
__device__ float g_hall [(size_t)TT * HH * BB];   // slot t holds h_{t+1}, [h][b]
__device__ float g_outs [(size_t)TT * OO * BB];   // [t][o][b]
__device__ unsigned g_hflag[8192];                // per-CTA ready flags, 128B apart

// -------- packed f32x2 helpers ----------
__device__ __forceinline__ unsigned long long pack2(float w) {
    unsigned long long r; unsigned u = __float_as_uint(w);
    asm("mov.b64 %0, {%1, %1};" : "=l"(r) : "r"(u));
    return r;
}
__device__ __forceinline__ void fma2(unsigned long long& d, unsigned long long a, unsigned long long b) {
    asm("fma.rn.f32x2 %0, %1, %2, %3;" : "=l"(d) : "l"(a), "l"(b), "l"(d));
}
__device__ __forceinline__ unsigned long long add2(unsigned long long a, unsigned long long b) {
    unsigned long long r;
    asm("add.rn.f32x2 %0, %1, %2;" : "=l"(r) : "l"(a), "l"(b));
    return r;
}
__device__ __forceinline__ void unpack2(float& lo, float& hi, unsigned long long v) {
    unsigned a, b;
    asm("mov.b64 {%0, %1}, %2;" : "=r"(a), "=r"(b) : "l"(v));
    lo = __uint_as_float(a); hi = __uint_as_float(b);
}
__device__ __forceinline__ unsigned ld_acq(const unsigned* p) {
    unsigned v;
    asm volatile("ld.acquire.gpu.global.u32 %0, [%1];" : "=r"(v) : "l"(p) : "memory");
    return v;
}
__device__ __forceinline__ void st_rel(unsigned* p, unsigned v) {
    asm volatile("st.release.gpu.global.u32 [%0], %1;" :: "l"(p), "r"(v) : "memory");
}

// ==========================================================================
// Kernel 0: zero flag state (every launch, before the scan)
// ==========================================================================
__global__ void flag_init_kernel() {
    for (int i = threadIdx.x; i < 8192; i += 256) g_hflag[i] = 0u;
}

// ==========================================================================
// Kernel 1: x_proj[t][h][b] = sum_i inputs[b][t][i] * w_in[h][i] + b_in[h]
// ==========================================================================
__global__ void __launch_bounds__(256) xproj_kernel(
    const float* __restrict__ inp, const float* __restrict__ w_in,
    const float* __restrict__ b_in)
{
    __shared__ float As[32][68];   // [i][h]
    __shared__ float Bs[32][68];   // [i][b]
    const int t = blockIdx.y;
    const int hbase = blockIdx.x << 6;
    const int tid = threadIdx.x;
    const int hg = tid >> 5;
    const int bg = tid & 31;

    unsigned long long acc[4][2];
#pragma unroll
    for (int p = 0; p < 4; ++p) { acc[p][0] = 0ull; acc[p][1] = 0ull; }

    for (int ic = 0; ic < II; ic += 32) {
#pragma unroll
        for (int n = tid; n < 64 * 32; n += 256) {
            int h = n >> 5, i = n & 31;
            As[i][h] = w_in[(size_t)(hbase + h) * II + ic + i];
        }
#pragma unroll
        for (int n = tid; n < 64 * 32; n += 256) {
            int b = n >> 5, i = n & 31;
            Bs[i][b] = inp[(size_t)b * (TT * II) + (size_t)t * II + ic + i];
        }
        __syncthreads();
#pragma unroll
        for (int i = 0; i < 32; ++i) {
            ulonglong2 w01 = *reinterpret_cast<const ulonglong2*>(&As[i][hg << 3]);
            ulonglong2 w23 = *reinterpret_cast<const ulonglong2*>(&As[i][(hg << 3) + 4]);
            float2 xv = *reinterpret_cast<const float2*>(&Bs[i][bg << 1]);
            unsigned long long x0 = pack2(xv.x), x1 = pack2(xv.y);
            fma2(acc[0][0], w01.x, x0); fma2(acc[0][1], w01.x, x1);
            fma2(acc[1][0], w01.y, x0); fma2(acc[1][1], w01.y, x1);
            fma2(acc[2][0], w23.x, x0); fma2(acc[2][1], w23.x, x1);
            fma2(acc[3][0], w23.y, x0); fma2(acc[3][1], w23.y, x1);
        }
        __syncthreads();
    }
#pragma unroll
    for (int p = 0; p < 4; ++p) {
        int h0 = hbase + (hg << 3) + 2 * p;
        float yA0, yA1, yB0, yB1;
        unpack2(yA0, yA1, acc[p][0]);
        unpack2(yB0, yB1, acc[p][1]);
        float bi0 = b_in[h0], bi1 = b_in[h0 + 1];
        size_t base = (size_t)t * (HH * BB) + (size_t)h0 * BB + (bg << 1);
        *reinterpret_cast<float2*>(g_xproj + base)      = make_float2(yA0 + bi0, yB0 + bi0);
        *reinterpret_cast<float2*>(g_xproj + base + BB) = make_float2(yA1 + bi1, yB1 + bi1);
    }
}

// ==========================================================================
// Kernel 2: persistent recurrent scan (W_rec only, 1024 rows).
// grid = 2 b-halves x nrg row-groups; 512 threads = 16 k-slices x 32 lanes.
// NO grid barrier: producer CTAs release a monotonic flag after writing their
// h rows; each warp acquire-polls only the flags of the groups its 64-k slice
// depends on. h slots are write-once per step -> RAW-only, no WAR.
// ==========================================================================
__global__ void __launch_bounds__(512, 1) rnn_step_kernel(
    const float* __restrict__ w_rec, const float* __restrict__ b_rec)
{
    extern __shared__ float smem[];
    float* Ws = smem;                                            // [1024 * MAXR]
    unsigned long long* red =
        reinterpret_cast<unsigned long long*>(smem + HH * MAXR); // [16][NPAIR][32]

    const int tid = threadIdx.x;
    const int cta = blockIdx.x;
    const int ncta = gridDim.x;
    const int nrg = ncta >> 1;
    const int rg = cta >> 1;
    const int bhalf = cta & 1;
    const int base_r = HH / nrg;
    const int extra = HH - base_r * nrg;
    const int row0 = rg * base_r + (rg < extra ? rg : extra);
    const int nrows = base_r + (rg < extra ? 1 : 0);

    // zero then stage weight rows once ([k][r], r stride MAXR)
    for (int idx = tid; idx < HH * MAXR; idx += 512) Ws[idx] = 0.f;
    __syncthreads();
    for (int r = 0; r < nrows; ++r) {
        const float* src = w_rec + (size_t)(row0 + r) * HH;
        for (int k = tid; k < HH; k += 512)
            Ws[k * MAXR + r] = src[k];
    }
    __syncthreads();

    const int lane = tid & 31;
    const int ks = tid >> 5;              // 0..15, 64 k each
    const int k0 = ks << 6;
    const int bglob = (bhalf << 5) + lane;

    // ---- producer groups covering this warp's k range [k0, k0+64) ----
    int g_lo = 0, g_hi = 0;
    {
        int r = 0, rs = 0;
        for (;;) {
            int rn = base_r + (r < extra ? 1 : 0);
            if (k0 < rs + rn) { g_lo = r; break; }
            rs += rn; ++r;
        }
        r = 0; rs = 0;
        for (;;) {
            int rn = base_r + (r < extra ? 1 : 0);
            if (k0 + 63 < rs + rn) { g_hi = r; break; }
            rs += rn; ++r;
        }
    }
    const int nflags = g_hi - g_lo + 1;   // <= 3

    // ---- epilogue role: tid < 224 handles (row-pair p_ep, batch b_ep)
    const bool has_ep = (tid < NPAIR * 32);
    const int p_ep = tid >> 5;
    const int b_ep = tid & 31;
    const int bg_ep = (bhalf << 5) + b_ep;
    int gr0 = 0, gr1 = 0;
    bool v0 = false, v1 = false;
    float a0 = 0.f, a1 = 0.f;
    if (has_ep) {
        int r0l = 2 * p_ep, r1l = 2 * p_ep + 1;
        v0 = r0l < nrows; v1 = r1l < nrows;
        gr0 = row0 + r0l; gr1 = row0 + r1l;
        if (v0) a0 = b_rec[gr0];
        if (v1) a1 = b_rec[gr1];
    }

#define LOADH(dst, off) do { \
    _Pragma("unroll") for (int u = 0; u < 16; ++u) (dst)[u] = hp[((off) + u) * BB]; } while (0)

#define COMPUTE16(buf) do { \
    _Pragma("unroll") for (int u = 0; u < 16; ++u) { \
        unsigned long long hv = pack2((buf)[u]); \
        ulonglong2 wA = *reinterpret_cast<const ulonglong2*>(wp); \
        ulonglong2 wB = *reinterpret_cast<const ulonglong2*>(wp + 4); \
        ulonglong2 wC = *reinterpret_cast<const ulonglong2*>(wp + 8); \
        unsigned long long wD = *reinterpret_cast<const unsigned long long*>(wp + 12); \
        wp += MAXR; \
        fma2(acc[0], wA.x, hv); fma2(acc[1], wA.y, hv); \
        fma2(acc[2], wB.x, hv); fma2(acc[3], wB.y, hv); \
        fma2(acc[4], wC.x, hv); fma2(acc[5], wC.y, hv); \
        fma2(acc[6], wD, hv); } } while (0)

    for (int j = 0; j < TT; ++j) {
        // prefetch epilogue x — independent of producer flags
        float x0 = 0.f, x1 = 0.f;
        if (has_ep) {
            if (v0) x0 = g_xproj[(size_t)j * (HH * BB) + (size_t)gr0 * BB + bg_ep];
            if (v1) x1 = g_xproj[(size_t)j * (HH * BB) + (size_t)gr1 * BB + bg_ep];
        }

        unsigned long long acc[NPAIR];
#pragma unroll
        for (int p = 0; p < NPAIR; ++p) acc[p] = 0ull;

        if (j > 0) {
            // ---- wait for the producers of this warp's k slice (lane 0 polls)
            if (lane == 0) {
#pragma unroll 1
                for (int f = 0; f < nflags; ++f) {
                    const unsigned* fp =
                        &g_hflag[(unsigned)((((g_lo + f) << 1) | bhalf)) << 5];
                    while (ld_acq(fp) < (unsigned)j) __nanosleep(50);
                }
            }
            __syncwarp();

            const float* hp = g_hall + (size_t)(j - 1) * (HH * BB) + (size_t)k0 * BB + bglob;
            const float* wp = Ws + k0 * MAXR;
            float hb0[16], hb1[16];
            LOADH(hb0, 0);
            LOADH(hb1, 16);
            COMPUTE16(hb0);
            LOADH(hb0, 32);
            COMPUTE16(hb1);
            LOADH(hb1, 48);
            COMPUTE16(hb0);
            COMPUTE16(hb1);
        }

        // k-slice reduction through SMEM
#pragma unroll
        for (int p = 0; p < NPAIR; ++p)
            red[(ks * NPAIR + p) * 32 + lane] = acc[p];
        __syncthreads();

        if (has_ep) {
            unsigned long long v[16];
#pragma unroll
            for (int q = 0; q < 16; ++q)
                v[q] = red[(q * NPAIR + p_ep) * 32 + b_ep];
            unsigned long long s01 = add2(add2(v[0], v[1]),  add2(v[2], v[3]));
            unsigned long long s23 = add2(add2(v[4], v[5]),  add2(v[6], v[7]));
            unsigned long long s45 = add2(add2(v[8], v[9]),  add2(v[10], v[11]));
            unsigned long long s67 = add2(add2(v[12], v[13]), add2(v[14], v[15]));
            unsigned long long s = add2(add2(s01, s23), add2(s45, s67));
            float y0, y1; unpack2(y0, y1, s);
            size_t base = (size_t)j * (HH * BB);
            if (v0) g_hall[base + (size_t)gr0 * BB + bg_ep] = fmaxf(y0 + a0 + x0, 0.0f);
            if (v1) g_hall[base + (size_t)gr1 * BB + bg_ep] = fmaxf(y1 + a1 + x1, 0.0f);
        }

        // ---- publish: release flag after all epilogue stores of this CTA ----
        __syncthreads();
        if (tid == 0)
            st_rel(&g_hflag[(unsigned)cta << 5], (unsigned)(j + 1));
    }
#undef LOADH
#undef COMPUTE16
}

// ==========================================================================
// Kernel 2b: out GEMM (off critical path), fp32 SIMT.
// ==========================================================================
__global__ void __launch_bounds__(256) outproj_kernel(
    const float* __restrict__ w_out, const float* __restrict__ b_out,
    const float* __restrict__ scale, const float* __restrict__ shift)
{
    __shared__ float As[32][68];
    __shared__ float Bs[32][68];
    const int t = blockIdx.y;
    const int obase = blockIdx.x << 6;
    const int tid = threadIdx.x;
    const int og = tid >> 5;
    const int bg = tid & 31;

    unsigned long long acc[4][2];
#pragma unroll
    for (int p = 0; p < 4; ++p) { acc[p][0] = 0ull; acc[p][1] = 0ull; }

    for (int kc = 0; kc < HH; kc += 32) {
#pragma unroll
        for (int n = tid; n < 64 * 32; n += 256) {
            int o = n >> 5, i = n & 31;
            As[i][o] = w_out[(size_t)(obase + o) * HH + kc + i];
        }
#pragma unroll
        for (int n = tid; n < 64 * 32; n += 256) {
            int b = n & 63, i = n >> 6;
            Bs[i][b] = g_hall[(size_t)t * (HH * BB) + (size_t)(kc + i) * BB + b];
        }
        __syncthreads();
#pragma unroll
        for (int i = 0; i < 32; ++i) {
            ulonglong2 w01 = *reinterpret_cast<const ulonglong2*>(&As[i][og << 3]);
            ulonglong2 w23 = *reinterpret_cast<const ulonglong2*>(&As[i][(og << 3) + 4]);
            float2 xv = *reinterpret_cast<const float2*>(&Bs[i][bg << 1]);
            unsigned long long x0 = pack2(xv.x), x1 = pack2(xv.y);
            fma2(acc[0][0], w01.x, x0); fma2(acc[0][1], w01.x, x1);
            fma2(acc[1][0], w01.y, x0); fma2(acc[1][1], w01.y, x1);
            fma2(acc[2][0], w23.x, x0); fma2(acc[2][1], w23.x, x1);
            fma2(acc[3][0], w23.y, x0); fma2(acc[3][1], w23.y, x1);
        }
        __syncthreads();
    }
#pragma unroll
    for (int p = 0; p < 4; ++p) {
        int o0 = obase + (og << 3) + 2 * p;
        float yA0, yA1, yB0, yB1;
        unpack2(yA0, yA1, acc[p][0]);
        unpack2(yB0, yB1, acc[p][1]);
        float m0 = scale[o0], m1 = scale[o0 + 1];
        float c0 = b_out[o0], c1 = b_out[o0 + 1];
        float s0 = shift[o0], s1 = shift[o0 + 1];
        size_t base = (size_t)t * (OO * BB) + (size_t)o0 * BB + (bg << 1);
        *reinterpret_cast<float2*>(g_outs + base) =
            make_float2(m0 * (yA0 + c0) - s0, m0 * (yB0 + c0) - s0);
        *reinterpret_cast<float2*>(g_outs + base + BB) =
            make_float2(m1 * (yA1 + c1) - s1, m1 * (yB1 + c1) - s1);
    }
}

// ==========================================================================
// Kernel 3: batched plane transpose  src[t][r][c] -> dst[c][t*R + r]
// ==========================================================================
__global__ void transpose_kernel(float* __restrict__ dst, int R, int which)
{
    __shared__ float tile[32][33];
    const float* src = which ? g_hall : g_outs;
    const int t = blockIdx.z;
    const int r0 = blockIdx.x << 5, c0 = blockIdx.y << 5;
    const int x = threadIdx.x, y = threadIdx.y;
    const float* s = src + (size_t)t * R * BB;
#pragma unroll
    for (int jj = 0; jj < 32; jj += 8)
        tile[y + jj][x] = s[(size_t)(r0 + y + jj) * BB + c0 + x];
    __syncthreads();
    const size_t TR = (size_t)TT * R;
#pragma unroll
    for (int jj = 0; jj < 32; jj += 8)
        dst[(size_t)(c0 + y + jj) * TR + (size_t)t * R + r0 + x] = tile[x][y + jj];
}

// ==========================================================================
extern "C" void kernel_launch(void* const* d_in, const int* in_sizes, int n_in,
                              void* d_out, int out_size)
{
    (void)in_sizes; (void)n_in; (void)out_size;
    const float* inputs = (const float*)d_in[0];
    const float* w_rec  = (const float*)d_in[1];
    const float* b_rec  = (const float*)d_in[2];
    const float* w_in   = (const float*)d_in[3];
    const float* b_in   = (const float*)d_in[4];
    const float* w_out  = (const float*)d_in[5];
    const float* b_out  = (const float*)d_in[6];
    const float* scale  = (const float*)d_in[7];
    const float* shift  = (const float*)d_in[8];
    float* out = (float*)d_out;

    flag_init_kernel<<<1, 256>>>();
    xproj_kernel<<<dim3(HH / 64, TT), 256>>>(inputs, w_in, b_in);

    int dev = 0, sms = 148;
    cudaGetDevice(&dev);
    cudaDeviceGetAttribute(&sms, cudaDevAttrMultiProcessorCount, dev);
    int ncta = sms & ~1;
    if (ncta > 152) ncta = 152;

    const int smem_bytes = HH * MAXR * 4 + 16 * NPAIR * 32 * 8;   // 65536 + 28672
    cudaFuncSetAttribute(rnn_step_kernel,
                         cudaFuncAttributeMaxDynamicSharedMemorySize, smem_bytes);
    rnn_step_kernel<<<ncta, 512, smem_bytes>>>(w_rec, b_rec);

    outproj_kernel<<<dim3(OO / 64, TT), 256>>>(w_out, b_out, scale, shift);

    transpose_kernel<<<dim3(OO / 32, BB / 32, TT), dim3(32, 8)>>>(out, OO, 0);
    transpose_kernel<<<dim3(HH / 32, BB / 32, TT), dim3(32, 8)>>>(
        out + (size_t)BB * TT * OO, HH, 1);
}

// round 8
// speedup vs baseline: 2.7585x; 1.6746x over previous
#include <cuda_runtime.h>
#include <cuda_bf16.h>
#include <cstdint>
#include <cstddef>

#define HH 1024
#define II 256
#define OO 256
#define BB 64
#define TT 512

// -------- static device scratch ----------
__device__ float g_xproj[(size_t)TT * HH * BB];   // [t][h][b]
__device__ float g_hall [(size_t)TT * HH * BB];   // slot t holds h_{t+1}, [h][b]
__device__ float g_outs [(size_t)TT * OO * BB];   // [t][o][b]
// B-fragment h buffer: [buf(2)][hi/lo(2)][kt(64)][nt(8)][lane(32)][reg(2)] u32
__device__ unsigned g_hfrag[2 * 2 * 64 * 8 * 32 * 2];
__device__ unsigned g_hflag[8192];                // per-CTA ready flags, 128B apart

// -------- packed f32x2 helpers (SIMT GEMM kernels) ----------
__device__ __forceinline__ unsigned long long pack2(float w) {
    unsigned long long r; unsigned u = __float_as_uint(w);
    asm("mov.b64 %0, {%1, %1};" : "=l"(r) : "r"(u));
    return r;
}
__device__ __forceinline__ void fma2(unsigned long long& d, unsigned long long a, unsigned long long b) {
    asm("fma.rn.f32x2 %0, %1, %2, %3;" : "=l"(d) : "l"(a), "l"(b), "l"(d));
}
__device__ __forceinline__ void unpack2(float& lo, float& hi, unsigned long long v) {
    unsigned a, b;
    asm("mov.b64 {%0, %1}, %2;" : "=r"(a), "=r"(b) : "l"(v));
    lo = __uint_as_float(a); hi = __uint_as_float(b);
}
__device__ __forceinline__ unsigned ld_acq(const unsigned* p) {
    unsigned v;
    asm volatile("ld.acquire.gpu.global.u32 %0, [%1];" : "=r"(v) : "l"(p) : "memory");
    return v;
}
__device__ __forceinline__ void st_rel(unsigned* p, unsigned v) {
    asm volatile("st.release.gpu.global.u32 [%0], %1;" :: "l"(p), "r"(v) : "memory");
}
__device__ __forceinline__ unsigned pack_bf16x2(float x, float y) {
    return (unsigned)__bfloat16_as_ushort(__float2bfloat16(x))
         | ((unsigned)__bfloat16_as_ushort(__float2bfloat16(y)) << 16);
}
__device__ __forceinline__ void mma_bf16(float* d, const unsigned* a, unsigned b0, unsigned b1) {
    asm volatile(
        "mma.sync.aligned.m16n8k16.row.col.f32.bf16.bf16.f32 "
        "{%0,%1,%2,%3}, {%4,%5,%6,%7}, {%8,%9}, {%0,%1,%2,%3};"
        : "+f"(d[0]), "+f"(d[1]), "+f"(d[2]), "+f"(d[3])
        : "r"(a[0]), "r"(a[1]), "r"(a[2]), "r"(a[3]), "r"(b0), "r"(b1));
}
__device__ __forceinline__ void ldcg_v2(unsigned& a, unsigned& b, const unsigned* p) {
    asm volatile("ld.global.cg.v2.u32 {%0,%1}, [%2];" : "=r"(a), "=r"(b) : "l"(p));
}

// ==========================================================================
// Kernel 0: zero flag state
// ==========================================================================
__global__ void flag_init_kernel() {
    for (int i = threadIdx.x; i < 8192; i += 256) g_hflag[i] = 0u;
}

// ==========================================================================
// Kernel 1: x_proj[t][h][b] = sum_i inputs[b][t][i] * w_in[h][i] + b_in[h]
// ==========================================================================
__global__ void __launch_bounds__(256) xproj_kernel(
    const float* __restrict__ inp, const float* __restrict__ w_in,
    const float* __restrict__ b_in)
{
    __shared__ float As[32][68];
    __shared__ float Bs[32][68];
    const int t = blockIdx.y;
    const int hbase = blockIdx.x << 6;
    const int tid = threadIdx.x;
    const int hg = tid >> 5;
    const int bg = tid & 31;

    unsigned long long acc[4][2];
#pragma unroll
    for (int p = 0; p < 4; ++p) { acc[p][0] = 0ull; acc[p][1] = 0ull; }

    for (int ic = 0; ic < II; ic += 32) {
#pragma unroll
        for (int n = tid; n < 64 * 32; n += 256) {
            int h = n >> 5, i = n & 31;
            As[i][h] = w_in[(size_t)(hbase + h) * II + ic + i];
        }
#pragma unroll
        for (int n = tid; n < 64 * 32; n += 256) {
            int b = n >> 5, i = n & 31;
            Bs[i][b] = inp[(size_t)b * (TT * II) + (size_t)t * II + ic + i];
        }
        __syncthreads();
#pragma unroll
        for (int i = 0; i < 32; ++i) {
            ulonglong2 w01 = *reinterpret_cast<const ulonglong2*>(&As[i][hg << 3]);
            ulonglong2 w23 = *reinterpret_cast<const ulonglong2*>(&As[i][(hg << 3) + 4]);
            float2 xv = *reinterpret_cast<const float2*>(&Bs[i][bg << 1]);
            unsigned long long x0 = pack2(xv.x), x1 = pack2(xv.y);
            fma2(acc[0][0], w01.x, x0); fma2(acc[0][1], w01.x, x1);
            fma2(acc[1][0], w01.y, x0); fma2(acc[1][1], w01.y, x1);
            fma2(acc[2][0], w23.x, x0); fma2(acc[2][1], w23.x, x1);
            fma2(acc[3][0], w23.y, x0); fma2(acc[3][1], w23.y, x1);
        }
        __syncthreads();
    }
#pragma unroll
    for (int p = 0; p < 4; ++p) {
        int h0 = hbase + (hg << 3) + 2 * p;
        float yA0, yA1, yB0, yB1;
        unpack2(yA0, yA1, acc[p][0]);
        unpack2(yB0, yB1, acc[p][1]);
        float bi0 = b_in[h0], bi1 = b_in[h0 + 1];
        size_t base = (size_t)t * (HH * BB) + (size_t)h0 * BB + (bg << 1);
        *reinterpret_cast<float2*>(g_xproj + base)      = make_float2(yA0 + bi0, yB0 + bi0);
        *reinterpret_cast<float2*>(g_xproj + base + BB) = make_float2(yA1 + bi1, yB1 + bi1);
    }
}

// ==========================================================================
// Kernel 2: mma.sync bf16 3-pass recurrent scan.
// 128 CTAs = 64 row-groups (M=16) x 2 batch-halves (N=32).
// 512 threads = 16 warps k-split (64 k each = 4 k-tiles of 16).
// A (W) resident in registers as mma fragments (hi+lo). h exchanged via a
// global B-fragment buffer (bf16 hi/lo, double-buffered), dataflow flags.
// ==========================================================================
__global__ void __launch_bounds__(512, 1) rnn_scan_mma_kernel(
    const float* __restrict__ w_rec, const float* __restrict__ b_rec)
{
    __shared__ float part[16 * 512];          // [w][slot] 32KB

    const int tid = threadIdx.x;
    const int w = tid >> 5;
    const int lane = tid & 31;
    const int cta = blockIdx.x;               // cta = g*2 + q
    const int g = cta >> 1;                   // row-group: rows [g*16, g*16+16)
    const int q = cta & 1;                    // batch half
    const int row0 = g << 4;

    // ---- build A fragments in registers (hi + lo), once ----
    unsigned Ahi[4][4], Alo[4][4];
    {
        const int gid = lane >> 2, tig = lane & 3;
        const int m0 = row0 + gid, m1 = row0 + gid + 8;
#pragma unroll
        for (int kt = 0; kt < 4; ++kt) {
            const int kb = (w * 4 + kt) * 16 + tig * 2;
            const float* r0 = w_rec + (size_t)m0 * HH + kb;
            const float* r1 = w_rec + (size_t)m1 * HH + kb;
            float e[8] = { r0[0], r0[1], r1[0], r1[1], r0[8], r0[9], r1[8], r1[9] };
#pragma unroll
            for (int p = 0; p < 4; ++p) {
                float x = e[2 * p], y = e[2 * p + 1];
                __nv_bfloat16 bx = __float2bfloat16(x), by = __float2bfloat16(y);
                Ahi[kt][p] = (unsigned)__bfloat16_as_ushort(bx)
                           | ((unsigned)__bfloat16_as_ushort(by) << 16);
                Alo[kt][p] = pack_bf16x2(x - __bfloat162float(bx),
                                         y - __bfloat162float(by));
            }
        }
    }

    // ---- epilogue slot mapping: tid -> (nt, L, reg) -> (m_local, n_local) ----
    const int ent_nt = tid >> 7;
    const int ent_L  = (tid >> 2) & 31;
    const int ent_reg = tid & 3;
    const int ent_gid = ent_L >> 2, ent_tig = ent_L & 3;
    const int m_local = ent_gid + ((ent_reg >> 1) << 3);
    const int n_local = ent_nt * 8 + ent_tig * 2 + (ent_reg & 1);
    const int k_glob = row0 + m_local;
    const int b_glob = (q << 5) + n_local;
    const float br = b_rec[k_glob];

    // fragment store addresses for the h value this thread produces
    const int st_NT = (q << 2) + (n_local >> 3);
    const int st_L  = (n_local & 7) * 4 + ((m_local >> 1) & 3);
    const int st_reg = m_local >> 3;
    const int st_pos = m_local & 1;
    const unsigned base_u32 = ((((unsigned)g << 3) + st_NT) * 32 + st_L) * 2 + st_reg;
    // (buf*2+hl)*32768 u32 stride
    unsigned short* sthi[2];
    unsigned short* stlo[2];
#pragma unroll
    for (int bf = 0; bf < 2; ++bf) {
        sthi[bf] = reinterpret_cast<unsigned short*>(&g_hfrag[(bf * 2 + 0) * 32768u + base_u32]) + st_pos;
        stlo[bf] = reinterpret_cast<unsigned short*>(&g_hfrag[(bf * 2 + 1) * 32768u + base_u32]) + st_pos;
    }

    for (int j = 0; j < TT; ++j) {
        const float xv = g_xproj[(size_t)j * (HH * BB) + (size_t)k_glob * BB + b_glob];

        float d[4][4];
#pragma unroll
        for (int nt = 0; nt < 4; ++nt)
#pragma unroll
            for (int p = 0; p < 4; ++p) d[nt][p] = 0.f;

        if (j > 0) {
            // wait for the 4 producer CTAs of this warp's k-tiles
            if (lane < 4) {
                const unsigned* fp = &g_hflag[(unsigned)(((w * 4 + lane) << 1) | q) << 5];
                while (ld_acq(fp) < (unsigned)j) __nanosleep(40);
            }
            __syncwarp();

            const unsigned rbase = ((unsigned)(j - 1) & 1u) * 65536u;
#pragma unroll
            for (int kt = 0; kt < 4; ++kt) {
                const int ktg = w * 4 + kt;
                unsigned bhi[4][2], blo[4][2];
#pragma unroll
                for (int nt = 0; nt < 4; ++nt) {
                    const unsigned off = (((unsigned)ktg * 8 + (q * 4 + nt)) * 32 + lane) * 2;
                    ldcg_v2(bhi[nt][0], bhi[nt][1], &g_hfrag[rbase + off]);
                    ldcg_v2(blo[nt][0], blo[nt][1], &g_hfrag[rbase + 32768u + off]);
                }
#pragma unroll
                for (int nt = 0; nt < 4; ++nt)
                    mma_bf16(d[nt], Ahi[kt], bhi[nt][0], bhi[nt][1]);
#pragma unroll
                for (int nt = 0; nt < 4; ++nt)
                    mma_bf16(d[nt], Ahi[kt], blo[nt][0], blo[nt][1]);
#pragma unroll
                for (int nt = 0; nt < 4; ++nt)
                    mma_bf16(d[nt], Alo[kt], bhi[nt][0], bhi[nt][1]);
            }
        }

        // ---- write partials [w][nt*128 + lane*4 + p] ----
#pragma unroll
        for (int nt = 0; nt < 4; ++nt)
            *reinterpret_cast<float4*>(&part[w * 512 + nt * 128 + lane * 4]) =
                make_float4(d[nt][0], d[nt][1], d[nt][2], d[nt][3]);
        __syncthreads();

        // ---- slot-major reduction over 16 warps (conflict-free) ----
        float y = 0.f;
#pragma unroll
        for (int w2 = 0; w2 < 16; ++w2) y += part[w2 * 512 + tid];

        const float h = fmaxf(y + br + xv, 0.0f);
        g_hall[(size_t)j * (HH * BB) + (size_t)k_glob * BB + b_glob] = h;
        const __nv_bfloat16 hh = __float2bfloat16(h);
        const int wb = j & 1;
        sthi[wb][0] = __bfloat16_as_ushort(hh);
        stlo[wb][0] = __bfloat16_as_ushort(__float2bfloat16(h - __bfloat162float(hh)));

        // ---- publish ----
        __syncthreads();
        if (tid == 0) {
            __threadfence();
            st_rel(&g_hflag[(unsigned)cta << 5], (unsigned)(j + 1));
        }
    }
}

// ==========================================================================
// Kernel 2b: out GEMM (off critical path), fp32 SIMT.
// ==========================================================================
__global__ void __launch_bounds__(256) outproj_kernel(
    const float* __restrict__ w_out, const float* __restrict__ b_out,
    const float* __restrict__ scale, const float* __restrict__ shift)
{
    __shared__ float As[32][68];
    __shared__ float Bs[32][68];
    const int t = blockIdx.y;
    const int obase = blockIdx.x << 6;
    const int tid = threadIdx.x;
    const int og = tid >> 5;
    const int bg = tid & 31;

    unsigned long long acc[4][2];
#pragma unroll
    for (int p = 0; p < 4; ++p) { acc[p][0] = 0ull; acc[p][1] = 0ull; }

    for (int kc = 0; kc < HH; kc += 32) {
#pragma unroll
        for (int n = tid; n < 64 * 32; n += 256) {
            int o = n >> 5, i = n & 31;
            As[i][o] = w_out[(size_t)(obase + o) * HH + kc + i];
        }
#pragma unroll
        for (int n = tid; n < 64 * 32; n += 256) {
            int b = n & 63, i = n >> 6;
            Bs[i][b] = g_hall[(size_t)t * (HH * BB) + (size_t)(kc + i) * BB + b];
        }
        __syncthreads();
#pragma unroll
        for (int i = 0; i < 32; ++i) {
            ulonglong2 w01 = *reinterpret_cast<const ulonglong2*>(&As[i][og << 3]);
            ulonglong2 w23 = *reinterpret_cast<const ulonglong2*>(&As[i][(og << 3) + 4]);
            float2 xv = *reinterpret_cast<const float2*>(&Bs[i][bg << 1]);
            unsigned long long x0 = pack2(xv.x), x1 = pack2(xv.y);
            fma2(acc[0][0], w01.x, x0); fma2(acc[0][1], w01.x, x1);
            fma2(acc[1][0], w01.y, x0); fma2(acc[1][1], w01.y, x1);
            fma2(acc[2][0], w23.x, x0); fma2(acc[2][1], w23.x, x1);
            fma2(acc[3][0], w23.y, x0); fma2(acc[3][1], w23.y, x1);
        }
        __syncthreads();
    }
#pragma unroll
    for (int p = 0; p < 4; ++p) {
        int o0 = obase + (og << 3) + 2 * p;
        float yA0, yA1, yB0, yB1;
        unpack2(yA0, yA1, acc[p][0]);
        unpack2(yB0, yB1, acc[p][1]);
        float m0 = scale[o0], m1 = scale[o0 + 1];
        float c0 = b_out[o0], c1 = b_out[o0 + 1];
        float s0 = shift[o0], s1 = shift[o0 + 1];
        size_t base = (size_t)t * (OO * BB) + (size_t)o0 * BB + (bg << 1);
        *reinterpret_cast<float2*>(g_outs + base) =
            make_float2(m0 * (yA0 + c0) - s0, m0 * (yB0 + c0) - s0);
        *reinterpret_cast<float2*>(g_outs + base + BB) =
            make_float2(m1 * (yA1 + c1) - s1, m1 * (yB1 + c1) - s1);
    }
}

// ==========================================================================
// Kernel 3: batched plane transpose  src[t][r][c] -> dst[c][t*R + r]
// ==========================================================================
__global__ void transpose_kernel(float* __restrict__ dst, int R, int which)
{
    __shared__ float tile[32][33];
    const float* src = which ? g_hall : g_outs;
    const int t = blockIdx.z;
    const int r0 = blockIdx.x << 5, c0 = blockIdx.y << 5;
    const int x = threadIdx.x, y = threadIdx.y;
    const float* s = src + (size_t)t * R * BB;
#pragma unroll
    for (int jj = 0; jj < 32; jj += 8)
        tile[y + jj][x] = s[(size_t)(r0 + y + jj) * BB + c0 + x];
    __syncthreads();
    const size_t TR = (size_t)TT * R;
#pragma unroll
    for (int jj = 0; jj < 32; jj += 8)
        dst[(size_t)(c0 + y + jj) * TR + (size_t)t * R + r0 + x] = tile[x][y + jj];
}

// ==========================================================================
extern "C" void kernel_launch(void* const* d_in, const int* in_sizes, int n_in,
                              void* d_out, int out_size)
{
    (void)in_sizes; (void)n_in; (void)out_size;
    const float* inputs = (const float*)d_in[0];
    const float* w_rec  = (const float*)d_in[1];
    const float* b_rec  = (const float*)d_in[2];
    const float* w_in   = (const float*)d_in[3];
    const float* b_in   = (const float*)d_in[4];
    const float* w_out  = (const float*)d_in[5];
    const float* b_out  = (const float*)d_in[6];
    const float* scale  = (const float*)d_in[7];
    const float* shift  = (const float*)d_in[8];
    float* out = (float*)d_out;

    flag_init_kernel<<<1, 256>>>();
    xproj_kernel<<<dim3(HH / 64, TT), 256>>>(inputs, w_in, b_in);

    rnn_scan_mma_kernel<<<128, 512>>>(w_rec, b_rec);

    outproj_kernel<<<dim3(OO / 64, TT), 256>>>(w_out, b_out, scale, shift);

    transpose_kernel<<<dim3(OO / 32, BB / 32, TT), dim3(32, 8)>>>(out, OO, 0);
    transpose_kernel<<<dim3(HH / 32, BB / 32, TT), dim3(32, 8)>>>(
        out + (size_t)BB * TT * OO, HH, 1);
}

// round 9
// speedup vs baseline: 2.9624x; 1.0739x over previous
#include <cuda_runtime.h>
#include <cuda_bf16.h>
#include <cstdint>
#include <cstddef>

#define HH 1024
#define II 256
#define OO 256
#define BB 64
#define TT 512

// -------- static device scratch ----------
__device__ float g_xproj[(size_t)TT * HH * BB];   // [t][h][b]
__device__ float g_hall [(size_t)TT * HH * BB];   // slot t holds h_{t+1}, [h][b]
__device__ float g_outs [(size_t)TT * OO * BB];   // [t][o][b]
// persistent B-fragment h buffer: [t][hi/lo][kt(64)][nt(8)][lane(32)][reg(2)] u32
// per-t block = 65536 u32 (hi at +0, lo at +32768)
__device__ unsigned g_hfrag[(size_t)TT * 65536];
__device__ unsigned g_hflag[8192];                // per-CTA ready flags, 128B apart

// -------- packed f32x2 helpers (SIMT kernels) ----------
__device__ __forceinline__ unsigned long long pack2(float w) {
    unsigned long long r; unsigned u = __float_as_uint(w);
    asm("mov.b64 %0, {%1, %1};" : "=l"(r) : "r"(u));
    return r;
}
__device__ __forceinline__ void fma2(unsigned long long& d, unsigned long long a, unsigned long long b) {
    asm("fma.rn.f32x2 %0, %1, %2, %3;" : "=l"(d) : "l"(a), "l"(b), "l"(d));
}
__device__ __forceinline__ void unpack2(float& lo, float& hi, unsigned long long v) {
    unsigned a, b;
    asm("mov.b64 {%0, %1}, %2;" : "=r"(a), "=r"(b) : "l"(v));
    lo = __uint_as_float(a); hi = __uint_as_float(b);
}
__device__ __forceinline__ unsigned ld_acq(const unsigned* p) {
    unsigned v;
    asm volatile("ld.acquire.gpu.global.u32 %0, [%1];" : "=r"(v) : "l"(p) : "memory");
    return v;
}
__device__ __forceinline__ void st_rel(unsigned* p, unsigned v) {
    asm volatile("st.release.gpu.global.u32 [%0], %1;" :: "l"(p), "r"(v) : "memory");
}
__device__ __forceinline__ unsigned pack_bf16x2(float x, float y) {
    return (unsigned)__bfloat16_as_ushort(__float2bfloat16(x))
         | ((unsigned)__bfloat16_as_ushort(__float2bfloat16(y)) << 16);
}
__device__ __forceinline__ void mma_bf16(float* d, const unsigned* a, unsigned b0, unsigned b1) {
    asm volatile(
        "mma.sync.aligned.m16n8k16.row.col.f32.bf16.bf16.f32 "
        "{%0,%1,%2,%3}, {%4,%5,%6,%7}, {%8,%9}, {%0,%1,%2,%3};"
        : "+f"(d[0]), "+f"(d[1]), "+f"(d[2]), "+f"(d[3])
        : "r"(a[0]), "r"(a[1]), "r"(a[2]), "r"(a[3]), "r"(b0), "r"(b1));
}
__device__ __forceinline__ void ldcg_v2(unsigned& a, unsigned& b, const unsigned* p) {
    asm volatile("ld.global.cg.v2.u32 {%0,%1}, [%2];" : "=r"(a), "=r"(b) : "l"(p));
}

// ==========================================================================
// Kernel 0: zero flag state
// ==========================================================================
__global__ void flag_init_kernel() {
    for (int i = threadIdx.x; i < 8192; i += 256) g_hflag[i] = 0u;
}

// ==========================================================================
// Kernel 1: x_proj[t][h][b] = sum_i inputs[b][t][i] * w_in[h][i] + b_in[h]
// ==========================================================================
__global__ void __launch_bounds__(256) xproj_kernel(
    const float* __restrict__ inp, const float* __restrict__ w_in,
    const float* __restrict__ b_in)
{
    __shared__ float As[32][68];
    __shared__ float Bs[32][68];
    const int t = blockIdx.y;
    const int hbase = blockIdx.x << 6;
    const int tid = threadIdx.x;
    const int hg = tid >> 5;
    const int bg = tid & 31;

    unsigned long long acc[4][2];
#pragma unroll
    for (int p = 0; p < 4; ++p) { acc[p][0] = 0ull; acc[p][1] = 0ull; }

    for (int ic = 0; ic < II; ic += 32) {
#pragma unroll
        for (int n = tid; n < 64 * 32; n += 256) {
            int h = n >> 5, i = n & 31;
            As[i][h] = w_in[(size_t)(hbase + h) * II + ic + i];
        }
#pragma unroll
        for (int n = tid; n < 64 * 32; n += 256) {
            int b = n >> 5, i = n & 31;
            Bs[i][b] = inp[(size_t)b * (TT * II) + (size_t)t * II + ic + i];
        }
        __syncthreads();
#pragma unroll
        for (int i = 0; i < 32; ++i) {
            ulonglong2 w01 = *reinterpret_cast<const ulonglong2*>(&As[i][hg << 3]);
            ulonglong2 w23 = *reinterpret_cast<const ulonglong2*>(&As[i][(hg << 3) + 4]);
            float2 xv = *reinterpret_cast<const float2*>(&Bs[i][bg << 1]);
            unsigned long long x0 = pack2(xv.x), x1 = pack2(xv.y);
            fma2(acc[0][0], w01.x, x0); fma2(acc[0][1], w01.x, x1);
            fma2(acc[1][0], w01.y, x0); fma2(acc[1][1], w01.y, x1);
            fma2(acc[2][0], w23.x, x0); fma2(acc[2][1], w23.x, x1);
            fma2(acc[3][0], w23.y, x0); fma2(acc[3][1], w23.y, x1);
        }
        __syncthreads();
    }
#pragma unroll
    for (int p = 0; p < 4; ++p) {
        int h0 = hbase + (hg << 3) + 2 * p;
        float yA0, yA1, yB0, yB1;
        unpack2(yA0, yA1, acc[p][0]);
        unpack2(yB0, yB1, acc[p][1]);
        float bi0 = b_in[h0], bi1 = b_in[h0 + 1];
        size_t base = (size_t)t * (HH * BB) + (size_t)h0 * BB + (bg << 1);
        *reinterpret_cast<float2*>(g_xproj + base)      = make_float2(yA0 + bi0, yB0 + bi0);
        *reinterpret_cast<float2*>(g_xproj + base + BB) = make_float2(yA1 + bi1, yB1 + bi1);
    }
}

// ==========================================================================
// Kernel 2: mma.sync bf16 3-pass recurrent scan.
// 128 CTAs = 64 row-groups (M=16) x 2 batch-halves (N=32).
// h exchanged via the PERSISTENT per-t fragment buffer (also consumed by
// outproj_mma afterwards). Dataflow flags, no grid barrier.
// ==========================================================================
__global__ void __launch_bounds__(512, 1) rnn_scan_mma_kernel(
    const float* __restrict__ w_rec, const float* __restrict__ b_rec)
{
    __shared__ float part[16 * 512];          // [w][slot] 32KB

    const int tid = threadIdx.x;
    const int w = tid >> 5;
    const int lane = tid & 31;
    const int cta = blockIdx.x;               // cta = g*2 + q
    const int g = cta >> 1;                   // row-group: rows [g*16, g*16+16)
    const int q = cta & 1;                    // batch half
    const int row0 = g << 4;

    // ---- build A fragments in registers (hi + lo), once ----
    unsigned Ahi[4][4], Alo[4][4];
    {
        const int gid = lane >> 2, tig = lane & 3;
        const int m0 = row0 + gid, m1 = row0 + gid + 8;
#pragma unroll
        for (int kt = 0; kt < 4; ++kt) {
            const int kb = (w * 4 + kt) * 16 + tig * 2;
            const float* r0 = w_rec + (size_t)m0 * HH + kb;
            const float* r1 = w_rec + (size_t)m1 * HH + kb;
            float e[8] = { r0[0], r0[1], r1[0], r1[1], r0[8], r0[9], r1[8], r1[9] };
#pragma unroll
            for (int p = 0; p < 4; ++p) {
                float x = e[2 * p], y = e[2 * p + 1];
                __nv_bfloat16 bx = __float2bfloat16(x), by = __float2bfloat16(y);
                Ahi[kt][p] = (unsigned)__bfloat16_as_ushort(bx)
                           | ((unsigned)__bfloat16_as_ushort(by) << 16);
                Alo[kt][p] = pack_bf16x2(x - __bfloat162float(bx),
                                         y - __bfloat162float(by));
            }
        }
    }

    // ---- epilogue slot mapping: tid -> (nt, L, reg) -> (m_local, n_local) ----
    const int ent_nt = tid >> 7;
    const int ent_L  = (tid >> 2) & 31;
    const int ent_reg = tid & 3;
    const int ent_gid = ent_L >> 2, ent_tig = ent_L & 3;
    const int m_local = ent_gid + ((ent_reg >> 1) << 3);
    const int n_local = ent_nt * 8 + ent_tig * 2 + (ent_reg & 1);
    const int k_glob = row0 + m_local;
    const int b_glob = (q << 5) + n_local;
    const float br = b_rec[k_glob];

    // fragment store base for the h value this thread produces (per-t stride
    // = 65536 u32 = 131072 u16)
    const int st_NT = (q << 2) + (n_local >> 3);
    const int st_L  = (n_local & 7) * 4 + ((m_local >> 1) & 3);
    const int st_reg = m_local >> 3;
    const int st_pos = m_local & 1;
    const unsigned base_u32 = ((((unsigned)g << 3) + st_NT) * 32 + st_L) * 2 + st_reg;
    unsigned short* sthi_base =
        reinterpret_cast<unsigned short*>(&g_hfrag[base_u32]) + st_pos;
    unsigned short* stlo_base =
        reinterpret_cast<unsigned short*>(&g_hfrag[32768u + base_u32]) + st_pos;

    for (int j = 0; j < TT; ++j) {
        const float xv = g_xproj[(size_t)j * (HH * BB) + (size_t)k_glob * BB + b_glob];

        float d[4][4];
#pragma unroll
        for (int nt = 0; nt < 4; ++nt)
#pragma unroll
            for (int p = 0; p < 4; ++p) d[nt][p] = 0.f;

        if (j > 0) {
            // wait for the 4 producer CTAs of this warp's k-tiles
            if (lane < 4) {
                const unsigned* fp = &g_hflag[(unsigned)(((w * 4 + lane) << 1) | q) << 5];
                while (ld_acq(fp) < (unsigned)j) __nanosleep(40);
            }
            __syncwarp();

            const size_t rbase = (size_t)(j - 1) * 65536u;
#pragma unroll
            for (int kt = 0; kt < 4; ++kt) {
                const int ktg = w * 4 + kt;
                unsigned bhi[4][2], blo[4][2];
#pragma unroll
                for (int nt = 0; nt < 4; ++nt) {
                    const unsigned off = (((unsigned)ktg * 8 + (q * 4 + nt)) * 32 + lane) * 2;
                    ldcg_v2(bhi[nt][0], bhi[nt][1], &g_hfrag[rbase + off]);
                    ldcg_v2(blo[nt][0], blo[nt][1], &g_hfrag[rbase + 32768u + off]);
                }
#pragma unroll
                for (int nt = 0; nt < 4; ++nt)
                    mma_bf16(d[nt], Ahi[kt], bhi[nt][0], bhi[nt][1]);
#pragma unroll
                for (int nt = 0; nt < 4; ++nt)
                    mma_bf16(d[nt], Ahi[kt], blo[nt][0], blo[nt][1]);
#pragma unroll
                for (int nt = 0; nt < 4; ++nt)
                    mma_bf16(d[nt], Alo[kt], bhi[nt][0], bhi[nt][1]);
            }
        }

        // ---- write partials [w][nt*128 + lane*4 + p] ----
#pragma unroll
        for (int nt = 0; nt < 4; ++nt)
            *reinterpret_cast<float4*>(&part[w * 512 + nt * 128 + lane * 4]) =
                make_float4(d[nt][0], d[nt][1], d[nt][2], d[nt][3]);
        __syncthreads();

        // ---- slot-major reduction over 16 warps (conflict-free) ----
        float y = 0.f;
#pragma unroll
        for (int w2 = 0; w2 < 16; ++w2) y += part[w2 * 512 + tid];

        const float h = fmaxf(y + br + xv, 0.0f);
        g_hall[(size_t)j * (HH * BB) + (size_t)k_glob * BB + b_glob] = h;
        const __nv_bfloat16 hh = __float2bfloat16(h);
        sthi_base[(size_t)j * 131072] = __bfloat16_as_ushort(hh);
        stlo_base[(size_t)j * 131072] =
            __bfloat16_as_ushort(__float2bfloat16(h - __bfloat162float(hh)));

        // ---- publish ----
        __syncthreads();
        if (tid == 0) {
            __threadfence();
            st_rel(&g_hflag[(unsigned)cta << 5], (unsigned)(j + 1));
        }
    }
}

// ==========================================================================
// Kernel 2b: out GEMM via mma.sync bf16 3-pass (off critical path).
// Reads B fragments directly from the persistent g_hfrag buffer.
// grid (8 o-groups of M=32, 16 t-chunks of 32). 512 thr = 2 m-tiles x 8 k-sl.
// ==========================================================================
__global__ void __launch_bounds__(512, 1) outproj_mma_kernel(
    const float* __restrict__ w_out, const float* __restrict__ b_out,
    const float* __restrict__ scale, const float* __restrict__ shift)
{
    __shared__ float part[2][8 * 2048];       // [buf][ksl][slot] 128KB

    const int tid = threadIdx.x;
    const int w = tid >> 5, lane = tid & 31;
    const int og = blockIdx.x;                // o rows [og*32, og*32+32)
    const int tc = blockIdx.y;                // t in [tc*32, tc*32+32)
    const int mt = w >> 3, ksl = w & 7;

    // ---- A fragments (w_out rows) hi + lo, 8 kt of 16 ----
    unsigned Ahi[8][4], Alo[8][4];
    {
        const int gid = lane >> 2, tig = lane & 3;
        const int m0 = og * 32 + mt * 16 + gid, m1 = m0 + 8;
#pragma unroll
        for (int kt = 0; kt < 8; ++kt) {
            const int kb = ksl * 128 + kt * 16 + tig * 2;
            const float* r0 = w_out + (size_t)m0 * HH + kb;
            const float* r1 = w_out + (size_t)m1 * HH + kb;
            float e[8] = { r0[0], r0[1], r1[0], r1[1], r0[8], r0[9], r1[8], r1[9] };
#pragma unroll
            for (int p = 0; p < 4; ++p) {
                float x = e[2 * p], y = e[2 * p + 1];
                __nv_bfloat16 bx = __float2bfloat16(x), by = __float2bfloat16(y);
                Ahi[kt][p] = (unsigned)__bfloat16_as_ushort(bx)
                           | ((unsigned)__bfloat16_as_ushort(by) << 16);
                Alo[kt][p] = pack_bf16x2(x - __bfloat162float(bx),
                                         y - __bfloat162float(by));
            }
        }
    }

    // ---- epilogue constants: thread owns slots [tid*4, tid*4+4) ----
    const int s0 = tid << 2;
    const int e_mt = s0 >> 10, e_nt = (s0 >> 7) & 7, e_L = (s0 >> 2) & 31;
    const int e_gid = e_L >> 2, e_tig = e_L & 3;
    const int m_lo = e_mt * 16 + e_gid;
    const int n0 = e_nt * 8 + e_tig * 2;
    const int o_lo = og * 32 + m_lo, o_hi = o_lo + 8;
    const float sc0 = scale[o_lo], sc1 = scale[o_hi];
    const float bo0 = b_out[o_lo], bo1 = b_out[o_hi];
    const float sh0 = shift[o_lo], sh1 = shift[o_hi];

    for (int tt = 0; tt < 32; ++tt) {
        const int t = tc * 32 + tt;
        const size_t tbase = (size_t)t * 65536u;

        float d[8][4];
#pragma unroll
        for (int nt = 0; nt < 8; ++nt)
#pragma unroll
            for (int p = 0; p < 4; ++p) d[nt][p] = 0.f;

#pragma unroll
        for (int kt = 0; kt < 8; ++kt) {
            const unsigned ktg = (unsigned)(ksl * 8 + kt);
            unsigned bh[8][2];
#pragma unroll
            for (int nt = 0; nt < 8; ++nt) {
                const unsigned off = (ktg * 8 + nt) * 64 + lane * 2;
                bh[nt][0] = g_hfrag[tbase + off];
                bh[nt][1] = g_hfrag[tbase + off + 1];
            }
#pragma unroll
            for (int nt = 0; nt < 8; ++nt)
                mma_bf16(d[nt], Ahi[kt], bh[nt][0], bh[nt][1]);
#pragma unroll
            for (int nt = 0; nt < 8; ++nt)
                mma_bf16(d[nt], Alo[kt], bh[nt][0], bh[nt][1]);
#pragma unroll
            for (int nt = 0; nt < 8; ++nt) {
                const unsigned off = (ktg * 8 + nt) * 64 + lane * 2;
                bh[nt][0] = g_hfrag[tbase + 32768u + off];
                bh[nt][1] = g_hfrag[tbase + 32768u + off + 1];
            }
#pragma unroll
            for (int nt = 0; nt < 8; ++nt)
                mma_bf16(d[nt], Ahi[kt], bh[nt][0], bh[nt][1]);
        }

        // ---- partials: slot = mt*1024 + nt*128 + lane*4 ----
        float* pb = part[tt & 1];
#pragma unroll
        for (int nt = 0; nt < 8; ++nt)
            *reinterpret_cast<float4*>(&pb[ksl * 2048 + mt * 1024 + nt * 128 + lane * 4]) =
                make_float4(d[nt][0], d[nt][1], d[nt][2], d[nt][3]);
        __syncthreads();

        // ---- reduce over 8 k-slices + fused epilogue ----
        float4 acc = make_float4(0.f, 0.f, 0.f, 0.f);
#pragma unroll
        for (int k2 = 0; k2 < 8; ++k2) {
            float4 v = *reinterpret_cast<const float4*>(&pb[k2 * 2048 + s0]);
            acc.x += v.x; acc.y += v.y; acc.z += v.z; acc.w += v.w;
        }
        size_t obase = (size_t)t * (OO * BB) + (size_t)o_lo * BB + n0;
        *reinterpret_cast<float2*>(g_outs + obase) =
            make_float2(sc0 * (acc.x + bo0) - sh0, sc0 * (acc.y + bo0) - sh0);
        *reinterpret_cast<float2*>(g_outs + obase + 8 * BB) =
            make_float2(sc1 * (acc.z + bo1) - sh1, sc1 * (acc.w + bo1) - sh1);
    }
}

// ==========================================================================
// Kernel 3: batched plane transpose  src[t][r][c] -> dst[c][t*R + r]
// ==========================================================================
__global__ void transpose_kernel(float* __restrict__ dst, int R, int which)
{
    __shared__ float tile[32][33];
    const float* src = which ? g_hall : g_outs;
    const int t = blockIdx.z;
    const int r0 = blockIdx.x << 5, c0 = blockIdx.y << 5;
    const int x = threadIdx.x, y = threadIdx.y;
    const float* s = src + (size_t)t * R * BB;
#pragma unroll
    for (int jj = 0; jj < 32; jj += 8)
        tile[y + jj][x] = s[(size_t)(r0 + y + jj) * BB + c0 + x];
    __syncthreads();
    const size_t TR = (size_t)TT * R;
#pragma unroll
    for (int jj = 0; jj < 32; jj += 8)
        dst[(size_t)(c0 + y + jj) * TR + (size_t)t * R + r0 + x] = tile[x][y + jj];
}

// ==========================================================================
extern "C" void kernel_launch(void* const* d_in, const int* in_sizes, int n_in,
                              void* d_out, int out_size)
{
    (void)in_sizes; (void)n_in; (void)out_size;
    const float* inputs = (const float*)d_in[0];
    const float* w_rec  = (const float*)d_in[1];
    const float* b_rec  = (const float*)d_in[2];
    const float* w_in   = (const float*)d_in[3];
    const float* b_in   = (const float*)d_in[4];
    const float* w_out  = (const float*)d_in[5];
    const float* b_out  = (const float*)d_in[6];
    const float* scale  = (const float*)d_in[7];
    const float* shift  = (const float*)d_in[8];
    float* out = (float*)d_out;

    flag_init_kernel<<<1, 256>>>();
    xproj_kernel<<<dim3(HH / 64, TT), 256>>>(inputs, w_in, b_in);

    rnn_scan_mma_kernel<<<128, 512>>>(w_rec, b_rec);

    outproj_mma_kernel<<<dim3(8, 16), 512>>>(w_out, b_out, scale, shift);

    transpose_kernel<<<dim3(OO / 32, BB / 32, TT), dim3(32, 8)>>>(out, OO, 0);
    transpose_kernel<<<dim3(HH / 32, BB / 32, TT), dim3(32, 8)>>>(
        out + (size_t)BB * TT * OO, HH, 1);
}